// round 13
// baseline (speedup 1.0000x reference)
#include <cuda_runtime.h>
#include <cuda_bf16.h>
#include <math.h>
#include <stdint.h>

// ---------------- problem constants ----------------
#define BSZ   256
#define H1S   12
#define P1    144
#define RTS   512
#define NCP   10
#define K1P   96
#define K2    20736
#define M1    (BSZ*P1)    // 36864
#define M2    4096
#define RECS  102400
#define DEC1  512
#define DEC2  1024
#define ZSPL  4
#define USLICE (M2 * 256)

// ---------------- scratch ----------------
__device__ __nv_bfloat16 g_A1h[M1 * K1P];
__device__ __nv_bfloat16 g_W1h[256 * K1P];
__device__ __nv_bfloat16 g_C1h[M1 * 256];
__device__ __nv_bfloat16 g_W2h[256 * K2];
__device__ float         g_Up[ZSPL * USLICE];
__device__ __nv_bfloat16 g_H1h[BSZ * DEC1];
__device__ __nv_bfloat16 g_H2h[BSZ * DEC2];
__device__ __nv_bfloat16 g_UH[(size_t)BSZ * RTS * 160];
__device__ float g_BIJ[RTS * NCP];
__device__ float g_V [BSZ * 160];
__device__ int   g_IDX[BSZ];

// ---------------- helpers ----------------
__device__ __forceinline__ uint32_t smem_u32(const void* p) {
    uint32_t a;
    asm("{ .reg .u64 t; cvta.to.shared.u64 t, %1; cvt.u32.u64 %0, t; }" : "=r"(a) : "l"(p));
    return a;
}
__device__ __forceinline__ void ldsm_x4(uint32_t addr, uint32_t* r) {
    asm volatile("ldmatrix.sync.aligned.m8n8.x4.shared.b16 {%0,%1,%2,%3}, [%4];"
        : "=r"(r[0]), "=r"(r[1]), "=r"(r[2]), "=r"(r[3]) : "r"(addr));
}
__device__ __forceinline__ void mma_bf16(float* c, const uint32_t* a, const uint32_t* b) {
    asm volatile(
        "mma.sync.aligned.m16n8k16.row.col.f32.bf16.bf16.f32 "
        "{%0,%1,%2,%3}, {%4,%5,%6,%7}, {%8,%9}, {%0,%1,%2,%3};"
        : "+f"(c[0]), "+f"(c[1]), "+f"(c[2]), "+f"(c[3])
        : "r"(a[0]), "r"(a[1]), "r"(a[2]), "r"(a[3]), "r"(b[0]), "r"(b[1]));
}
__device__ __forceinline__ uint4 pack8bf16(float4 f0, float4 f1) {
    __nv_bfloat162 p0 = __halves2bfloat162(__float2bfloat16(f0.x), __float2bfloat16(f0.y));
    __nv_bfloat162 p1 = __halves2bfloat162(__float2bfloat16(f0.z), __float2bfloat16(f0.w));
    __nv_bfloat162 p2 = __halves2bfloat162(__float2bfloat16(f1.x), __float2bfloat16(f1.y));
    __nv_bfloat162 p3 = __halves2bfloat162(__float2bfloat16(f1.z), __float2bfloat16(f1.w));
    uint4 r;
    r.x = *reinterpret_cast<uint32_t*>(&p0);
    r.y = *reinterpret_cast<uint32_t*>(&p1);
    r.z = *reinterpret_cast<uint32_t*>(&p2);
    r.w = *reinterpret_cast<uint32_t*>(&p3);
    return r;
}
__device__ __forceinline__ void cp16(uint32_t d, const void* s) {
    asm volatile("cp.async.cg.shared.global [%0], [%1], 16;" :: "r"(d), "l"(s));
}
__device__ __forceinline__ void cp_commit() { asm volatile("cp.async.commit_group;"); }
template<int NW> __device__ __forceinline__ void cp_wait() {
    asm volatile("cp.async.wait_group %0;" :: "n"(NW));
}

// ============ async HMMA bf16 NT GEMM, BM=128 BN=128 BK=32, 256 thr, 2 CTA/SM ============
template<int MODE, int ACT, int OUT, int SPLITK, int STAGES>
__global__ __launch_bounds__(256, 2)
void hmma_gemm_async(const __nv_bfloat16* __restrict__ Ah,
                     const __nv_bfloat16* __restrict__ Wh,
                     const float* __restrict__ bias,
                     float* __restrict__ Cf,
                     __nv_bfloat16* __restrict__ Coh,
                     int N, int K)
{
    extern __shared__ char sm[];
    constexpr int AP   = 80;
    constexpr int ABYT = 128 * AP;
    constexpr int STG  = 2 * ABYT;   // 20480

    const int t = threadIdx.x;
    const int m0 = blockIdx.x * 128;
    const int n0 = blockIdx.y * 128;
    const uint32_t sbase = smem_u32(sm);

    int r4[2], s4[2], mbase[2];
#pragma unroll
    for (int i = 0; i < 2; i++) {
        int idx = t + i * 256;
        r4[i] = idx >> 2; s4[i] = idx & 3;
        if (MODE == 1) {
            int m = m0 + r4[i]; int b = m >> 4, p = m & 15;
            mbase[i] = b * 144 + (p >> 2) * 12 + (p & 3);
        }
    }

    const int w = t >> 5, lane = t & 31;
    const int wm = w >> 1, wn = w & 1;          // 4x2 warps, 32x64 tile
    const int lrow = (lane & 7) + ((lane >> 3) & 1) * 8;
    const int lk   = ((lane >> 4) & 1) * 8;

    float acc[2][8][4];
#pragma unroll
    for (int mt = 0; mt < 2; mt++)
#pragma unroll
        for (int nt = 0; nt < 8; nt++)
#pragma unroll
            for (int q = 0; q < 4; q++) acc[mt][nt][q] = 0.f;

    auto issue = [&](int s, int k0) {
        uint32_t sb = sbase + (s % STAGES) * STG;
#pragma unroll
        for (int i = 0; i < 2; i++) {
            size_t aoff;
            if (MODE == 0) {
                aoff = (size_t)(m0 + r4[i]) * K + k0 + s4[i] * 8;
            } else {
                int rr = k0 >> 8;
                int rowg = mbase[i] + (rr / 9) * 12 + (rr % 9);
                aoff = (size_t)rowg * 256 + (k0 & 255) + s4[i] * 8;
            }
            cp16(sb + r4[i] * AP + s4[i] * 16, Ah + aoff);
            cp16(sb + ABYT + r4[i] * AP + s4[i] * 16,
                 Wh + (size_t)(n0 + r4[i]) * K + k0 + s4[i] * 8);
        }
    };
    auto compute = [&](int buf) {
        uint32_t base = sbase + buf * STG;
#pragma unroll
        for (int kk = 0; kk < 32; kk += 16) {
            uint32_t a_h[2][4], b_h[4][4];
#pragma unroll
            for (int mt = 0; mt < 2; mt++) {
                uint32_t ad = base + (wm * 32 + mt * 16 + lrow) * AP + (kk + lk) * 2;
                ldsm_x4(ad, a_h[mt]);
            }
#pragma unroll
            for (int np = 0; np < 4; np++) {
                uint32_t bd = base + ABYT + (wn * 64 + np * 16 + lrow) * AP + (kk + lk) * 2;
                ldsm_x4(bd, b_h[np]);
            }
#pragma unroll
            for (int mt = 0; mt < 2; mt++)
#pragma unroll
                for (int nt = 0; nt < 8; nt++)
                    mma_bf16(acc[mt][nt], a_h[mt], &b_h[nt >> 1][(nt & 1) * 2]);
        }
    };

    const int S = SPLITK ? (K / 32 / ZSPL) : (K / 32);
    const int kbase = SPLITK ? blockIdx.z * (K / ZSPL) : 0;
#pragma unroll
    for (int p = 0; p < STAGES - 1; p++) {
        if (p < S) issue(p, kbase + p * 32);
        cp_commit();
    }
    for (int s = 0; s < S; s++) {
        cp_wait<STAGES - 2>();
        __syncthreads();
        if (s + STAGES - 1 < S) issue(s + STAGES - 1, kbase + (s + STAGES - 1) * 32);
        cp_commit();
        compute(s % STAGES);
    }

    // ---- epilogue ----
    const size_t zoff = SPLITK ? (size_t)blockIdx.z * (size_t)(gridDim.x * 128) * N : 0;
#pragma unroll
    for (int mt = 0; mt < 2; mt++) {
#pragma unroll
        for (int nt = 0; nt < 8; nt++) {
            int row0 = m0 + wm * 32 + mt * 16 + (lane >> 2);
            int col  = n0 + wn * 64 + nt * 8 + (lane & 3) * 2;
            float b0, b1;
            if (SPLITK && blockIdx.z != 0) { b0 = 0.f; b1 = 0.f; }
            else { b0 = bias[col]; b1 = bias[col + 1]; }
#pragma unroll
            for (int half = 0; half < 2; half++) {
                int row = row0 + half * 8;
                float v0 = acc[mt][nt][half * 2 + 0] + b0;
                float v1 = acc[mt][nt][half * 2 + 1] + b1;
                if (ACT == 1) { v0 = fmaxf(v0, 0.f); v1 = fmaxf(v1, 0.f); }
                if (OUT == 0) {
                    *reinterpret_cast<float2*>(&Cf[zoff + (size_t)row * N + col]) = make_float2(v0, v1);
                } else {
                    *reinterpret_cast<__nv_bfloat162*>(&Coh[(size_t)row * N + col]) =
                        __halves2bfloat162(__float2bfloat16(v0), __float2bfloat16(v1));
                }
            }
        }
    }
}

// ============ 2-stage HMMA GEMM, fp32 W converted in loader, 256 thr ============
template<int ACT, int OUT>
__global__ __launch_bounds__(256, 2)
void hmma_gemm_wf(const __nv_bfloat16* __restrict__ Ah,
                  const float* __restrict__ Wf,
                  const float* __restrict__ bias,
                  float* __restrict__ Cf,
                  __nv_bfloat16* __restrict__ Coh,
                  int N, int K)
{
    extern __shared__ char sm[];
    constexpr int AP   = 80;
    constexpr int ABYT = 128 * AP;
    constexpr int STG  = 2 * ABYT;

    const int t = threadIdx.x;
    const int m0 = blockIdx.x * 128;
    const int n0 = blockIdx.y * 128;
    const uint32_t sbase = smem_u32(sm);

    int r4[2], s4[2];
#pragma unroll
    for (int i = 0; i < 2; i++) {
        int idx = t + i * 256;
        r4[i] = idx >> 2; s4[i] = idx & 3;
    }
    const int w = t >> 5, lane = t & 31;
    const int wm = w >> 1, wn = w & 1;
    const int lrow = (lane & 7) + ((lane >> 3) & 1) * 8;
    const int lk   = ((lane >> 4) & 1) * 8;

    float acc[2][8][4];
#pragma unroll
    for (int mt = 0; mt < 2; mt++)
#pragma unroll
        for (int nt = 0; nt < 8; nt++)
#pragma unroll
            for (int q = 0; q < 4; q++) acc[mt][nt][q] = 0.f;

    uint4 rA[2], rB[2];
    auto ldg_stage = [&](int k0) {
#pragma unroll
        for (int i = 0; i < 2; i++) {
            rA[i] = *(const uint4*)(Ah + (size_t)(m0 + r4[i]) * K + k0 + s4[i] * 8);
            const float* wp = Wf + (size_t)(n0 + r4[i]) * K + k0 + s4[i] * 8;
            rB[i] = pack8bf16(*(const float4*)wp, *(const float4*)(wp + 4));
        }
    };
    auto sts_stage = [&](int buf) {
        char* p = sm + buf * STG;
#pragma unroll
        for (int i = 0; i < 2; i++) {
            *(uint4*)(p + r4[i] * AP + s4[i] * 16) = rA[i];
            *(uint4*)(p + ABYT + r4[i] * AP + s4[i] * 16) = rB[i];
        }
    };
    auto compute = [&](int buf) {
        uint32_t base = sbase + buf * STG;
#pragma unroll
        for (int kk = 0; kk < 32; kk += 16) {
            uint32_t a_h[2][4], b_h[4][4];
#pragma unroll
            for (int mt = 0; mt < 2; mt++) {
                uint32_t ad = base + (wm * 32 + mt * 16 + lrow) * AP + (kk + lk) * 2;
                ldsm_x4(ad, a_h[mt]);
            }
#pragma unroll
            for (int np = 0; np < 4; np++) {
                uint32_t bd = base + ABYT + (wn * 64 + np * 16 + lrow) * AP + (kk + lk) * 2;
                ldsm_x4(bd, b_h[np]);
            }
#pragma unroll
            for (int mt = 0; mt < 2; mt++)
#pragma unroll
                for (int nt = 0; nt < 8; nt++)
                    mma_bf16(acc[mt][nt], a_h[mt], &b_h[nt >> 1][(nt & 1) * 2]);
        }
    };

    const int S = K / 32;
    ldg_stage(0);
    sts_stage(0);
    __syncthreads();
    for (int s = 0; s < S; s++) {
        if (s + 1 < S) ldg_stage((s + 1) * 32);
        compute(s & 1);
        if (s + 1 < S) sts_stage((s + 1) & 1);
        __syncthreads();
    }

#pragma unroll
    for (int mt = 0; mt < 2; mt++) {
#pragma unroll
        for (int nt = 0; nt < 8; nt++) {
            int row0 = m0 + wm * 32 + mt * 16 + (lane >> 2);
            int col  = n0 + wn * 64 + nt * 8 + (lane & 3) * 2;
            float b0 = bias[col], b1 = bias[col + 1];
#pragma unroll
            for (int half = 0; half < 2; half++) {
                int row = row0 + half * 8;
                float v0 = acc[mt][nt][half * 2 + 0] + b0;
                float v1 = acc[mt][nt][half * 2 + 1] + b1;
                if (ACT == 1) { v0 = fmaxf(v0, 0.f); v1 = fmaxf(v1, 0.f); }
                else if (ACT == 2) {
                    v0 = 1.f / (1.f + expf(-v0));
                    v1 = 1.f / (1.f + expf(-v1));
                }
                if (OUT == 0) {
                    *reinterpret_cast<float2*>(&Cf[(size_t)row * N + col]) = make_float2(v0, v1);
                } else {
                    *reinterpret_cast<__nv_bfloat162*>(&Coh[(size_t)row * N + col]) =
                        __halves2bfloat162(__float2bfloat16(v0), __float2bfloat16(v1));
                }
            }
        }
    }
}

// ---------------- prep kernels ----------------
__global__ void im2col1_kernel(const float* __restrict__ data) {
    int idx = blockIdx.x * blockDim.x + threadIdx.x;
    if (idx >= M1 * K1P) return;
    int m = idx / K1P, kk = idx % K1P;
    float v = 0.f;
    if (kk < 81) {
        int b = m / P1, pos = m % P1;
        int y = pos / H1S, x = pos % H1S;
        int ky = kk / 9, kx = kk % 9;
        v = data[(size_t)b * 400 + (y + ky) * 20 + (x + kx)];
    }
    g_A1h[idx] = __float2bfloat16(v);
}
__global__ void permute_w1_kernel(const float* __restrict__ conv1_w) {
    int idx = blockIdx.x * blockDim.x + threadIdx.x;
    if (idx >= 256 * K1P) return;
    int o = idx / K1P, kk = idx % K1P;
    float v = (kk < 81) ? conv1_w[o * 81 + kk] : 0.f;
    g_W1h[idx] = __float2bfloat16(v);
}
__global__ void permute_w2_kernel(const float* __restrict__ prim_w) {
    __shared__ __nv_bfloat16 sm[K2];
    int o = blockIdx.x;
    int t = threadIdx.x;
    const float* src = prim_w + (size_t)o * K2;
    for (int idx = t; idx < K2; idx += 256)
        sm[idx] = __float2bfloat16(src[idx]);
    __syncthreads();
    __nv_bfloat16* dst = g_W2h + (size_t)o * K2;
    for (int idx = t; idx < K2; idx += 256) {
        int rr = idx >> 8, c = idx & 255;
        dst[idx] = sm[c * 81 + rr];
    }
}

// ---------------- fused squash + u_hat ----------------
__global__ void uhat_kernel(const float* __restrict__ Wd) {
    int r = blockIdx.x;
    int b0 = blockIdx.y * 32;
    int t = threadIdx.x;       // 160: t = c*16+o
    __shared__ float Wr[1280];
    __shared__ float Xr[256];
    for (int q = t; q < 1280; q += 160) Wr[q] = Wd[(size_t)r * 1280 + q];
    int oo = r >> 1, hi = r & 1;
    for (int q = t; q < 256; q += 160) {
        int b = q >> 3, i = q & 7;
        size_t base = (size_t)((b0 + b) * 16 + hi * 8 + i) * 256 + oo;
        float v = g_Up[base];
#pragma unroll
        for (int z = 1; z < ZSPL; z++) v += g_Up[(size_t)z * USLICE + base];
        Xr[q] = v;
    }
    __syncthreads();
    if (t < 32) {
        float u[8], sn = 0.f;
#pragma unroll
        for (int i = 0; i < 8; i++) { u[i] = Xr[t * 8 + i]; sn += u[i] * u[i]; }
        float sc = sn / ((1.f + sn) * sqrtf(sn));
#pragma unroll
        for (int i = 0; i < 8; i++) Xr[t * 8 + i] = u[i] * sc;
    }
    __syncthreads();
    for (int b = 0; b < 32; b++) {
        float acc = 0.f;
#pragma unroll
        for (int i = 0; i < 8; i++) acc = fmaf(Wr[t * 8 + i], Xr[b * 8 + i], acc);
        g_UH[(size_t)((b0 + b) * RTS + r) * 160 + t] = __float2bfloat16(acc);
    }
}

// ---- fused routing passes 1&2: u_hat[b] smem-resident; softmax in-block ----
template<int UNIFORM>
__global__ __launch_bounds__(512)
void route_fused_kernel(float* __restrict__ agp) {
    extern __shared__ float smr[];               // [512*81] UH words, then cs[5120]
    float* cs = smr + 512 * 81;
    __shared__ float v_s[160];
    __shared__ float s_mx[NCP], s_sum[NCP];
    const int b = blockIdx.x;
    const int t = threadIdx.x;
    const int w = t >> 5, lane = t & 31;

    const uint32_t* src = reinterpret_cast<const uint32_t*>(&g_UH[(size_t)b * RTS * 160]);
    uint32_t* uw = reinterpret_cast<uint32_t*>(smr);
    for (int q = t; q < RTS * 80; q += 512) {
        int r = q / 80, ww = q - r * 80;
        uw[r * 81 + ww] = src[q];
    }
    if (!UNIFORM) {
        for (int q = t; q < RTS * NCP; q += 512) cs[q] = g_BIJ[q];
    }
    __syncthreads();

    if (!UNIFORM) {
        if (w < NCP) {
            float m = -1e30f;
            for (int r = lane; r < RTS; r += 32) m = fmaxf(m, cs[r * NCP + w]);
#pragma unroll
            for (int o = 16; o; o >>= 1) m = fmaxf(m, __shfl_xor_sync(0xFFFFFFFFu, m, o));
            float ssum = 0.f;
            for (int r = lane; r < RTS; r += 32) ssum += expf(cs[r * NCP + w] - m);
#pragma unroll
            for (int o = 16; o; o >>= 1) ssum += __shfl_xor_sync(0xFFFFFFFFu, ssum, o);
            if (lane == 0) { s_mx[w] = m; s_sum[w] = ssum; }
        }
        __syncthreads();
        for (int q = t; q < RTS * NCP; q += 512) {
            int j = q % NCP;
            cs[q] = expf(cs[q] - s_mx[j]) / s_sum[j];
        }
        __syncthreads();
    }

    if (t < 160) {
        int j = t >> 4;
        int wdx = t >> 1, hi = t & 1;
        float acc = 0.f;
        for (int r = 0; r < RTS; r++) {
            uint32_t u2 = uw[r * 81 + wdx];
            float2 a = __bfloat1622float2(*reinterpret_cast<__nv_bfloat162*>(&u2));
            float u = hi ? a.y : a.x;
            float c = UNIFORM ? (1.f / 512.f) : cs[r * NCP + j];
            acc = fmaf(c, u, acc);
        }
        float sq = acc * acc;
        float v = sq * acc / ((1.f + sq) * sqrtf(sq));
        v_s[t] = v;
    }
    __syncthreads();

    {
        int r = t;
        const uint32_t* row = uw + r * 81;
#pragma unroll
        for (int j = 0; j < NCP; j++) {
            float d = 0.f;
#pragma unroll
            for (int ww = 0; ww < 8; ww++) {
                uint32_t u2 = row[j * 8 + ww];
                float2 a = __bfloat1622float2(*reinterpret_cast<__nv_bfloat162*>(&u2));
                d += a.x * v_s[j * 16 + ww * 2] + a.y * v_s[j * 16 + ww * 2 + 1];
            }
            agp[(size_t)b * 5120 + j * 512 + r] = d;
        }
    }
}

// ---- pass 3: direct-global s->v (no smem staging of UH) ----
__global__ __launch_bounds__(160)
void route_sv_final_kernel() {
    __shared__ float cs[RTS * NCP];
    __shared__ float mx[NCP], sum[NCP];
    const int b = blockIdx.x;
    const int t = threadIdx.x;   // 160
    for (int q = t; q < RTS * NCP; q += 160) cs[q] = g_BIJ[q];
    __syncthreads();
    if (t < NCP) {
        float m = -1e30f;
        for (int r = 0; r < RTS; r++) m = fmaxf(m, cs[r * NCP + t]);
        float s = 0.f;
        for (int r = 0; r < RTS; r++) s += expf(cs[r * NCP + t] - m);
        mx[t] = m; sum[t] = s;
    }
    __syncthreads();
    int j = t >> 4;
    const __nv_bfloat16* uh = &g_UH[(size_t)b * RTS * 160 + t];
    float acc = 0.f;
    for (int r = 0; r < RTS; r++) {
        float c = expf(cs[r * NCP + j] - mx[j]) / sum[j];
        acc = fmaf(c, __bfloat162float(uh[(size_t)r * 160]), acc);
    }
    float sq = acc * acc;
    g_V[b * 160 + t] = sq * acc / ((1.f + sq) * sqrtf(sq));
}

__global__ void route_reduce_kernel(const float* __restrict__ agp, int first) {
    int q = blockIdx.x * 512 + threadIdx.x;   // 5120
    float s = 0.f;
    for (int b = 0; b < BSZ; b++) s += agp[(size_t)b * 5120 + q];
    int j = q >> 9, r = q & 511;
    float val = s * (1.f / 256.f);
    if (first) g_BIJ[r * NCP + j] = val;
    else       g_BIJ[r * NCP + j] += val;
}
__global__ void classes_argmax_kernel() {
    int b = threadIdx.x; // 256
    __shared__ float cl[256 * NCP];
    __shared__ float lz[NCP];
    for (int j = 0; j < NCP; j++) {
        float s = 0.f;
        for (int o = 0; o < 16; o++) {
            float v = g_V[b * 160 + j * 16 + o];
            s += v * v;
        }
        cl[b * NCP + j] = sqrtf(s);
    }
    __syncthreads();
    if (b < NCP) {
        float m = -1e30f;
        for (int q = 0; q < 256; q++) m = fmaxf(m, cl[q * NCP + b]);
        float s = 0.f;
        for (int q = 0; q < 256; q++) s += expf(cl[q * NCP + b] - m);
        lz[b] = m + logf(s);
    }
    __syncthreads();
    int best = 0;
    float bv = cl[b * NCP + 0] - lz[0];
    for (int j = 1; j < NCP; j++) {
        float v = cl[b * NCP + j] - lz[j];
        if (v > bv) { bv = v; best = j; }
    }
    g_IDX[b] = best;
}
__global__ void dec1_kernel(const float* __restrict__ w1, const float* __restrict__ b1) {
    int b = blockIdx.x;    // 256
    int k = threadIdx.x;   // 512
    __shared__ float vs[16];
    __shared__ int idx;
    if (k == 0) idx = g_IDX[b];
    __syncthreads();
    if (k < 16) vs[k] = g_V[b * 160 + idx * 16 + k];
    __syncthreads();
    float acc = b1[k];
    const float* wp = &w1[(size_t)k * 160 + idx * 16];
#pragma unroll
    for (int o = 0; o < 16; o++) acc = fmaf(vs[o], wp[o], acc);
    g_H1h[b * DEC1 + k] = __float2bfloat16(fmaxf(acc, 0.f));
}

// ---------------- launch ----------------
extern "C" void kernel_launch(void* const* d_in, const int* in_sizes, int n_in,
                              void* d_out, int out_size) {
    const float* data    = (const float*)d_in[0];
    const float* conv1_w = (const float*)d_in[1];
    const float* conv1_b = (const float*)d_in[2];
    const float* prim_w  = (const float*)d_in[3];
    const float* prim_b  = (const float*)d_in[4];
    const float* W_digit = (const float*)d_in[5];
    const float* dec_w1  = (const float*)d_in[6];
    const float* dec_b1  = (const float*)d_in[7];
    const float* dec_w2  = (const float*)d_in[8];
    const float* dec_b2  = (const float*)d_in[9];
    const float* dec_w3  = (const float*)d_in[10];
    const float* dec_b3  = (const float*)d_in[11];
    float* out = (float*)d_out;

    __nv_bfloat16 *pA1h, *pW1h, *pC1h, *pW2h, *pH1h, *pH2h;
    float *pUp;
    cudaGetSymbolAddress((void**)&pA1h, g_A1h);
    cudaGetSymbolAddress((void**)&pW1h, g_W1h);
    cudaGetSymbolAddress((void**)&pC1h, g_C1h);
    cudaGetSymbolAddress((void**)&pW2h, g_W2h);
    cudaGetSymbolAddress((void**)&pH1h, g_H1h);
    cudaGetSymbolAddress((void**)&pH2h, g_H2h);
    cudaGetSymbolAddress((void**)&pUp, g_Up);

    constexpr int SMA3 = 3 * 20480;                 // conv1: 3-stage
    constexpr int SMA4 = 4 * 20480;                 // prim: 4-stage
    constexpr int SMB  = 2 * 20480;                 // wf 2-stage
    constexpr int SMR  = 512 * 81 * 4 + 5120 * 4;   // fused routing
    cudaFuncSetAttribute((const void*)hmma_gemm_async<0, 1, 2, 0, 3>, cudaFuncAttributeMaxDynamicSharedMemorySize, SMA3);
    cudaFuncSetAttribute((const void*)hmma_gemm_async<1, 0, 0, 1, 4>, cudaFuncAttributeMaxDynamicSharedMemorySize, SMA4);
    cudaFuncSetAttribute((const void*)hmma_gemm_wf<1, 2>, cudaFuncAttributeMaxDynamicSharedMemorySize, SMB);
    cudaFuncSetAttribute((const void*)hmma_gemm_wf<2, 0>, cudaFuncAttributeMaxDynamicSharedMemorySize, SMB);
    cudaFuncSetAttribute((const void*)route_fused_kernel<1>, cudaFuncAttributeMaxDynamicSharedMemorySize, SMR);
    cudaFuncSetAttribute((const void*)route_fused_kernel<0>, cudaFuncAttributeMaxDynamicSharedMemorySize, SMR);

    // weight preps
    permute_w1_kernel<<<(256 * K1P + 255) / 256, 256>>>(conv1_w);
    permute_w2_kernel<<<256, 256>>>(prim_w);

    // 1) conv1: async bf16 HMMA (K=96, 3 stages), relu, bf16 out
    im2col1_kernel<<<(M1 * K1P + 255) / 256, 256>>>(data);
    hmma_gemm_async<0, 1, 2, 0, 3><<<dim3(M1 / 128, 256 / 128), 256, SMA3>>>(
        pA1h, pW1h, conv1_b, nullptr, pC1h, 256, K1P);

    // 2) primary caps: implicit im2col async (4 stages), split-K=4 partials
    hmma_gemm_async<1, 0, 0, 1, 4><<<dim3(M2 / 128, 256 / 128, ZSPL), 256, SMA4>>>(
        pC1h, pW2h, prim_b, pUp, nullptr, 256, K2);

    // 3) fused squash + u_hat (bf16 out)
    uhat_kernel<<<dim3(RTS, 8), 160>>>(W_digit);

    // 4) fused dynamic routing
    route_fused_kernel<1><<<BSZ, 512, SMR>>>(pUp);
    route_reduce_kernel<<<10, 512>>>(pUp, 1);
    route_fused_kernel<0><<<BSZ, 512, SMR>>>(pUp);
    route_reduce_kernel<<<10, 512>>>(pUp, 0);
    route_sv_final_kernel<<<BSZ, 160>>>();

    // 5) classes / mask / decoder
    classes_argmax_kernel<<<1, 256>>>();
    dec1_kernel<<<BSZ, DEC1>>>(dec_w1, dec_b1);
    hmma_gemm_wf<1, 2><<<dim3(BSZ / 128, DEC2 / 128), 256, SMB>>>(
        pH1h, dec_w2, dec_b2, nullptr, pH2h, DEC2, DEC1);
    hmma_gemm_wf<2, 0><<<dim3(BSZ / 128, RECS / 128), 256, SMB>>>(
        pH2h, dec_w3, dec_b3, out, nullptr, RECS, DEC2);
}

// round 14
// speedup vs baseline: 1.1104x; 1.1104x over previous
#include <cuda_runtime.h>
#include <cuda_bf16.h>
#include <math.h>
#include <stdint.h>

// ---------------- problem constants ----------------
#define BSZ   256
#define H1S   12
#define P1    144
#define RTS   512
#define NCP   10
#define K1P   96
#define K2    20736
#define M1    (BSZ*P1)    // 36864
#define M2    4096
#define RECS  102400
#define DEC1  512
#define DEC2  1024
#define ZSPL  4
#define USLICE (M2 * 256)

// ---------------- scratch ----------------
__device__ __nv_bfloat16 g_A1h[M1 * K1P];
__device__ __nv_bfloat16 g_W1h[256 * K1P];
__device__ __nv_bfloat16 g_C1h[M1 * 256];
__device__ __nv_bfloat16 g_W2h[256 * K2];
__device__ float         g_Up[ZSPL * USLICE];   // split-K partials; reused as agreement partials
__device__ __nv_bfloat16 g_H1h[BSZ * DEC1];
__device__ __nv_bfloat16 g_H2h[BSZ * DEC2];
__device__ __nv_bfloat16 g_UH[(size_t)BSZ * RTS * 160];
__device__ float g_BIJ[RTS * NCP];
__device__ float g_V [BSZ * 160];
__device__ int   g_IDX[BSZ];

// ---------------- helpers ----------------
__device__ __forceinline__ uint32_t smem_u32(const void* p) {
    uint32_t a;
    asm("{ .reg .u64 t; cvta.to.shared.u64 t, %1; cvt.u32.u64 %0, t; }" : "=r"(a) : "l"(p));
    return a;
}
__device__ __forceinline__ void ldsm_x4(uint32_t addr, uint32_t* r) {
    asm volatile("ldmatrix.sync.aligned.m8n8.x4.shared.b16 {%0,%1,%2,%3}, [%4];"
        : "=r"(r[0]), "=r"(r[1]), "=r"(r[2]), "=r"(r[3]) : "r"(addr));
}
__device__ __forceinline__ void mma_bf16(float* c, const uint32_t* a, const uint32_t* b) {
    asm volatile(
        "mma.sync.aligned.m16n8k16.row.col.f32.bf16.bf16.f32 "
        "{%0,%1,%2,%3}, {%4,%5,%6,%7}, {%8,%9}, {%0,%1,%2,%3};"
        : "+f"(c[0]), "+f"(c[1]), "+f"(c[2]), "+f"(c[3])
        : "r"(a[0]), "r"(a[1]), "r"(a[2]), "r"(a[3]), "r"(b[0]), "r"(b[1]));
}
__device__ __forceinline__ uint4 pack8bf16(float4 f0, float4 f1) {
    __nv_bfloat162 p0 = __halves2bfloat162(__float2bfloat16(f0.x), __float2bfloat16(f0.y));
    __nv_bfloat162 p1 = __halves2bfloat162(__float2bfloat16(f0.z), __float2bfloat16(f0.w));
    __nv_bfloat162 p2 = __halves2bfloat162(__float2bfloat16(f1.x), __float2bfloat16(f1.y));
    __nv_bfloat162 p3 = __halves2bfloat162(__float2bfloat16(f1.z), __float2bfloat16(f1.w));
    uint4 r;
    r.x = *reinterpret_cast<uint32_t*>(&p0);
    r.y = *reinterpret_cast<uint32_t*>(&p1);
    r.z = *reinterpret_cast<uint32_t*>(&p2);
    r.w = *reinterpret_cast<uint32_t*>(&p3);
    return r;
}
__device__ __forceinline__ void cp16(uint32_t d, const void* s) {
    asm volatile("cp.async.cg.shared.global [%0], [%1], 16;" :: "r"(d), "l"(s));
}
__device__ __forceinline__ void cp_commit() { asm volatile("cp.async.commit_group;"); }
template<int NW> __device__ __forceinline__ void cp_wait() {
    asm volatile("cp.async.wait_group %0;" :: "n"(NW));
}

// ============ async HMMA bf16 NT GEMM, BM=128 BN=128 BK=32, 256 thr (8 warps 4x2) ============
template<int MODE, int ACT, int OUT, int SPLITK, int STAGES>
__global__ __launch_bounds__(256)
void hmma_gemm_async(const __nv_bfloat16* __restrict__ Ah,
                     const __nv_bfloat16* __restrict__ Wh,
                     const float* __restrict__ bias,
                     float* __restrict__ Cf,
                     __nv_bfloat16* __restrict__ Coh,
                     int N, int K)
{
    extern __shared__ char sm[];
    constexpr int AP   = 80;
    constexpr int ABYT = 128 * AP;
    constexpr int STG  = 2 * ABYT;   // 20480

    const int t = threadIdx.x;
    const int m0 = blockIdx.x * 128;
    const int n0 = blockIdx.y * 128;
    const uint32_t sbase = smem_u32(sm);

    int r4[2], s4[2], mbase[2];
#pragma unroll
    for (int i = 0; i < 2; i++) {
        int idx = t + i * 256;
        r4[i] = idx >> 2; s4[i] = idx & 3;
        if (MODE == 1) {
            int m = m0 + r4[i]; int b = m >> 4, p = m & 15;
            mbase[i] = b * 144 + (p >> 2) * 12 + (p & 3);
        }
    }

    const int w = t >> 5, lane = t & 31;
    const int wm = w >> 1, wn = w & 1;          // 4x2 warps, 32x64 tile
    const int lrow = (lane & 7) + ((lane >> 3) & 1) * 8;
    const int lk   = ((lane >> 4) & 1) * 8;

    float acc[2][8][4];
#pragma unroll
    for (int mt = 0; mt < 2; mt++)
#pragma unroll
        for (int nt = 0; nt < 8; nt++)
#pragma unroll
            for (int q = 0; q < 4; q++) acc[mt][nt][q] = 0.f;

    auto issue = [&](int s, int k0) {
        uint32_t sb = sbase + (s % STAGES) * STG;
#pragma unroll
        for (int i = 0; i < 2; i++) {
            size_t aoff;
            if (MODE == 0) {
                aoff = (size_t)(m0 + r4[i]) * K + k0 + s4[i] * 8;
            } else {
                int rr = k0 >> 8;
                int rowg = mbase[i] + (rr / 9) * 12 + (rr % 9);
                aoff = (size_t)rowg * 256 + (k0 & 255) + s4[i] * 8;
            }
            cp16(sb + r4[i] * AP + s4[i] * 16, Ah + aoff);
            cp16(sb + ABYT + r4[i] * AP + s4[i] * 16,
                 Wh + (size_t)(n0 + r4[i]) * K + k0 + s4[i] * 8);
        }
    };
    auto compute = [&](int buf) {
        uint32_t base = sbase + buf * STG;
#pragma unroll
        for (int kk = 0; kk < 32; kk += 16) {
            uint32_t a_h[2][4], b_h[4][4];
#pragma unroll
            for (int mt = 0; mt < 2; mt++) {
                uint32_t ad = base + (wm * 32 + mt * 16 + lrow) * AP + (kk + lk) * 2;
                ldsm_x4(ad, a_h[mt]);
            }
#pragma unroll
            for (int np = 0; np < 4; np++) {
                uint32_t bd = base + ABYT + (wn * 64 + np * 16 + lrow) * AP + (kk + lk) * 2;
                ldsm_x4(bd, b_h[np]);
            }
#pragma unroll
            for (int mt = 0; mt < 2; mt++)
#pragma unroll
                for (int nt = 0; nt < 8; nt++)
                    mma_bf16(acc[mt][nt], a_h[mt], &b_h[nt >> 1][(nt & 1) * 2]);
        }
    };

    const int S = SPLITK ? (K / 32 / ZSPL) : (K / 32);
    const int kbase = SPLITK ? blockIdx.z * (K / ZSPL) : 0;
#pragma unroll
    for (int p = 0; p < STAGES - 1; p++) {
        if (p < S) issue(p, kbase + p * 32);
        cp_commit();
    }
    for (int s = 0; s < S; s++) {
        cp_wait<STAGES - 2>();
        __syncthreads();
        if (s + STAGES - 1 < S) issue(s + STAGES - 1, kbase + (s + STAGES - 1) * 32);
        cp_commit();
        compute(s % STAGES);
    }

    // ---- epilogue ----
    const size_t zoff = SPLITK ? (size_t)blockIdx.z * (size_t)(gridDim.x * 128) * N : 0;
#pragma unroll
    for (int mt = 0; mt < 2; mt++) {
#pragma unroll
        for (int nt = 0; nt < 8; nt++) {
            int row0 = m0 + wm * 32 + mt * 16 + (lane >> 2);
            int col  = n0 + wn * 64 + nt * 8 + (lane & 3) * 2;
            float b0, b1;
            if (SPLITK && blockIdx.z != 0) { b0 = 0.f; b1 = 0.f; }
            else { b0 = bias[col]; b1 = bias[col + 1]; }
#pragma unroll
            for (int half = 0; half < 2; half++) {
                int row = row0 + half * 8;
                float v0 = acc[mt][nt][half * 2 + 0] + b0;
                float v1 = acc[mt][nt][half * 2 + 1] + b1;
                if (ACT == 1) { v0 = fmaxf(v0, 0.f); v1 = fmaxf(v1, 0.f); }
                if (OUT == 0) {
                    *reinterpret_cast<float2*>(&Cf[zoff + (size_t)row * N + col]) = make_float2(v0, v1);
                } else {
                    *reinterpret_cast<__nv_bfloat162*>(&Coh[(size_t)row * N + col]) =
                        __halves2bfloat162(__float2bfloat16(v0), __float2bfloat16(v1));
                }
            }
        }
    }
}

// ============ 2-stage HMMA GEMM, fp32 W converted in loader, 256 thr ============
template<int ACT, int OUT>
__global__ __launch_bounds__(256)
void hmma_gemm_wf(const __nv_bfloat16* __restrict__ Ah,
                  const float* __restrict__ Wf,
                  const float* __restrict__ bias,
                  float* __restrict__ Cf,
                  __nv_bfloat16* __restrict__ Coh,
                  int N, int K)
{
    extern __shared__ char sm[];
    constexpr int AP   = 80;
    constexpr int ABYT = 128 * AP;
    constexpr int STG  = 2 * ABYT;

    const int t = threadIdx.x;
    const int m0 = blockIdx.x * 128;
    const int n0 = blockIdx.y * 128;
    const uint32_t sbase = smem_u32(sm);

    int r4[2], s4[2];
#pragma unroll
    for (int i = 0; i < 2; i++) {
        int idx = t + i * 256;
        r4[i] = idx >> 2; s4[i] = idx & 3;
    }
    const int w = t >> 5, lane = t & 31;
    const int wm = w >> 1, wn = w & 1;
    const int lrow = (lane & 7) + ((lane >> 3) & 1) * 8;
    const int lk   = ((lane >> 4) & 1) * 8;

    float acc[2][8][4];
#pragma unroll
    for (int mt = 0; mt < 2; mt++)
#pragma unroll
        for (int nt = 0; nt < 8; nt++)
#pragma unroll
            for (int q = 0; q < 4; q++) acc[mt][nt][q] = 0.f;

    uint4 rA[2], rB[2];
    auto ldg_stage = [&](int k0) {
#pragma unroll
        for (int i = 0; i < 2; i++) {
            rA[i] = *(const uint4*)(Ah + (size_t)(m0 + r4[i]) * K + k0 + s4[i] * 8);
            const float* wp = Wf + (size_t)(n0 + r4[i]) * K + k0 + s4[i] * 8;
            rB[i] = pack8bf16(*(const float4*)wp, *(const float4*)(wp + 4));
        }
    };
    auto sts_stage = [&](int buf) {
        char* p = sm + buf * STG;
#pragma unroll
        for (int i = 0; i < 2; i++) {
            *(uint4*)(p + r4[i] * AP + s4[i] * 16) = rA[i];
            *(uint4*)(p + ABYT + r4[i] * AP + s4[i] * 16) = rB[i];
        }
    };
    auto compute = [&](int buf) {
        uint32_t base = sbase + buf * STG;
#pragma unroll
        for (int kk = 0; kk < 32; kk += 16) {
            uint32_t a_h[2][4], b_h[4][4];
#pragma unroll
            for (int mt = 0; mt < 2; mt++) {
                uint32_t ad = base + (wm * 32 + mt * 16 + lrow) * AP + (kk + lk) * 2;
                ldsm_x4(ad, a_h[mt]);
            }
#pragma unroll
            for (int np = 0; np < 4; np++) {
                uint32_t bd = base + ABYT + (wn * 64 + np * 16 + lrow) * AP + (kk + lk) * 2;
                ldsm_x4(bd, b_h[np]);
            }
#pragma unroll
            for (int mt = 0; mt < 2; mt++)
#pragma unroll
                for (int nt = 0; nt < 8; nt++)
                    mma_bf16(acc[mt][nt], a_h[mt], &b_h[nt >> 1][(nt & 1) * 2]);
        }
    };

    const int S = K / 32;
    ldg_stage(0);
    sts_stage(0);
    __syncthreads();
    for (int s = 0; s < S; s++) {
        if (s + 1 < S) ldg_stage((s + 1) * 32);
        compute(s & 1);
        if (s + 1 < S) sts_stage((s + 1) & 1);
        __syncthreads();
    }

#pragma unroll
    for (int mt = 0; mt < 2; mt++) {
#pragma unroll
        for (int nt = 0; nt < 8; nt++) {
            int row0 = m0 + wm * 32 + mt * 16 + (lane >> 2);
            int col  = n0 + wn * 64 + nt * 8 + (lane & 3) * 2;
            float b0 = bias[col], b1 = bias[col + 1];
#pragma unroll
            for (int half = 0; half < 2; half++) {
                int row = row0 + half * 8;
                float v0 = acc[mt][nt][half * 2 + 0] + b0;
                float v1 = acc[mt][nt][half * 2 + 1] + b1;
                if (ACT == 1) { v0 = fmaxf(v0, 0.f); v1 = fmaxf(v1, 0.f); }
                else if (ACT == 2) {
                    v0 = 1.f / (1.f + expf(-v0));
                    v1 = 1.f / (1.f + expf(-v1));
                }
                if (OUT == 0) {
                    *reinterpret_cast<float2*>(&Cf[(size_t)row * N + col]) = make_float2(v0, v1);
                } else {
                    *reinterpret_cast<__nv_bfloat162*>(&Coh[(size_t)row * N + col]) =
                        __halves2bfloat162(__float2bfloat16(v0), __float2bfloat16(v1));
                }
            }
        }
    }
}

// ---------------- prep kernels ----------------
__global__ void im2col1_kernel(const float* __restrict__ data) {
    int idx = blockIdx.x * blockDim.x + threadIdx.x;
    if (idx >= M1 * K1P) return;
    int m = idx / K1P, kk = idx % K1P;
    float v = 0.f;
    if (kk < 81) {
        int b = m / P1, pos = m % P1;
        int y = pos / H1S, x = pos % H1S;
        int ky = kk / 9, kx = kk % 9;
        v = data[(size_t)b * 400 + (y + ky) * 20 + (x + kx)];
    }
    g_A1h[idx] = __float2bfloat16(v);
}
__global__ void permute_w1_kernel(const float* __restrict__ conv1_w) {
    int idx = blockIdx.x * blockDim.x + threadIdx.x;
    if (idx >= 256 * K1P) return;
    int o = idx / K1P, kk = idx % K1P;
    float v = (kk < 81) ? conv1_w[o * 81 + kk] : 0.f;
    g_W1h[idx] = __float2bfloat16(v);
}
__global__ void permute_w2_kernel(const float* __restrict__ prim_w) {
    __shared__ __nv_bfloat16 sm[K2];
    int o = blockIdx.x;
    int t = threadIdx.x;
    const float* src = prim_w + (size_t)o * K2;
    for (int idx = t; idx < K2; idx += 256)
        sm[idx] = __float2bfloat16(src[idx]);
    __syncthreads();
    __nv_bfloat16* dst = g_W2h + (size_t)o * K2;
    for (int idx = t; idx < K2; idx += 256) {
        int rr = idx >> 8, c = idx & 255;
        dst[idx] = sm[c * 81 + rr];
    }
}

// ---------------- fused squash + u_hat ----------------
// block (r, b0-chunk); reduces split-K partials, squashes, then u_hat for 32 batches.
__global__ void uhat_kernel(const float* __restrict__ Wd) {
    int r = blockIdx.x;
    int b0 = blockIdx.y * 32;
    int t = threadIdx.x;       // 160: t = c*16+o
    __shared__ float Wr[1280];
    __shared__ float Xr[256];
    for (int q = t; q < 1280; q += 160) Wr[q] = Wd[(size_t)r * 1280 + q];
    int oo = r >> 1, hi = r & 1;
    for (int q = t; q < 256; q += 160) {
        int b = q >> 3, i = q & 7;
        size_t base = (size_t)((b0 + b) * 16 + hi * 8 + i) * 256 + oo;
        float v = g_Up[base];
#pragma unroll
        for (int z = 1; z < ZSPL; z++) v += g_Up[(size_t)z * USLICE + base];
        Xr[q] = v;
    }
    __syncthreads();
    if (t < 32) {
        float u[8], sn = 0.f;
#pragma unroll
        for (int i = 0; i < 8; i++) { u[i] = Xr[t * 8 + i]; sn += u[i] * u[i]; }
        float sc = sn / ((1.f + sn) * sqrtf(sn));
#pragma unroll
        for (int i = 0; i < 8; i++) Xr[t * 8 + i] = u[i] * sc;
    }
    __syncthreads();
    for (int b = 0; b < 32; b++) {
        float acc = 0.f;
#pragma unroll
        for (int i = 0; i < 8; i++) acc = fmaf(Wr[t * 8 + i], Xr[b * 8 + i], acc);
        g_UH[(size_t)((b0 + b) * RTS + r) * 160 + t] = __float2bfloat16(acc);
    }
}

// ---- fused routing: one block per b; u_hat[b] smem-resident; softmax in-block ----
template<int UNIFORM, int AGREE, int WRITEV>
__global__ __launch_bounds__(512)
void route_fused_kernel(float* __restrict__ agp) {
    extern __shared__ float smr[];               // [512*81] UH words, then cs[5120]
    float* cs = smr + 512 * 81;
    __shared__ float v_s[160];
    __shared__ float s_mx[NCP], s_sum[NCP];
    const int b = blockIdx.x;
    const int t = threadIdx.x;
    const int w = t >> 5, lane = t & 31;

    const uint32_t* src = reinterpret_cast<const uint32_t*>(&g_UH[(size_t)b * RTS * 160]);
    uint32_t* uw = reinterpret_cast<uint32_t*>(smr);
    for (int q = t; q < RTS * 80; q += 512) {
        int r = q / 80, ww = q - r * 80;
        uw[r * 81 + ww] = src[q];
    }
    if (!UNIFORM) {
        for (int q = t; q < RTS * NCP; q += 512) cs[q] = g_BIJ[q];
    }
    __syncthreads();

    if (!UNIFORM) {
        if (w < NCP) {
            float m = -1e30f;
            for (int r = lane; r < RTS; r += 32) m = fmaxf(m, cs[r * NCP + w]);
#pragma unroll
            for (int o = 16; o; o >>= 1) m = fmaxf(m, __shfl_xor_sync(0xFFFFFFFFu, m, o));
            float ssum = 0.f;
            for (int r = lane; r < RTS; r += 32) ssum += expf(cs[r * NCP + w] - m);
#pragma unroll
            for (int o = 16; o; o >>= 1) ssum += __shfl_xor_sync(0xFFFFFFFFu, ssum, o);
            if (lane == 0) { s_mx[w] = m; s_sum[w] = ssum; }
        }
        __syncthreads();
        for (int q = t; q < RTS * NCP; q += 512) {
            int j = q % NCP;
            cs[q] = expf(cs[q] - s_mx[j]) / s_sum[j];
        }
        __syncthreads();
    }

    if (t < 160) {
        int j = t >> 4;
        int wdx = t >> 1, hi = t & 1;
        float acc = 0.f;
        for (int r = 0; r < RTS; r++) {
            uint32_t u2 = uw[r * 81 + wdx];
            float2 a = __bfloat1622float2(*reinterpret_cast<__nv_bfloat162*>(&u2));
            float u = hi ? a.y : a.x;
            float c = UNIFORM ? (1.f / 512.f) : cs[r * NCP + j];
            acc = fmaf(c, u, acc);
        }
        float sq = acc * acc;
        float v = sq * acc / ((1.f + sq) * sqrtf(sq));
        v_s[t] = v;
        if (WRITEV) g_V[b * 160 + t] = v;
    }
    __syncthreads();

    if (AGREE) {
        int r = t;
        const uint32_t* row = uw + r * 81;
#pragma unroll
        for (int j = 0; j < NCP; j++) {
            float d = 0.f;
#pragma unroll
            for (int ww = 0; ww < 8; ww++) {
                uint32_t u2 = row[j * 8 + ww];
                float2 a = __bfloat1622float2(*reinterpret_cast<__nv_bfloat162*>(&u2));
                d += a.x * v_s[j * 16 + ww * 2] + a.y * v_s[j * 16 + ww * 2 + 1];
            }
            agp[(size_t)b * 5120 + j * 512 + r] = d;
        }
    }
}
__global__ void route_reduce_kernel(const float* __restrict__ agp, int first) {
    int q = blockIdx.x * 512 + threadIdx.x;   // 5120
    float s = 0.f;
    for (int b = 0; b < BSZ; b++) s += agp[(size_t)b * 5120 + q];
    int j = q >> 9, r = q & 511;
    float val = s * (1.f / 256.f);
    if (first) g_BIJ[r * NCP + j] = val;
    else       g_BIJ[r * NCP + j] += val;
}
__global__ void classes_argmax_kernel() {
    int b = threadIdx.x; // 256
    __shared__ float cl[256 * NCP];
    __shared__ float lz[NCP];
    for (int j = 0; j < NCP; j++) {
        float s = 0.f;
        for (int o = 0; o < 16; o++) {
            float v = g_V[b * 160 + j * 16 + o];
            s += v * v;
        }
        cl[b * NCP + j] = sqrtf(s);
    }
    __syncthreads();
    if (b < NCP) {
        float m = -1e30f;
        for (int q = 0; q < 256; q++) m = fmaxf(m, cl[q * NCP + b]);
        float s = 0.f;
        for (int q = 0; q < 256; q++) s += expf(cl[q * NCP + b] - m);
        lz[b] = m + logf(s);
    }
    __syncthreads();
    int best = 0;
    float bv = cl[b * NCP + 0] - lz[0];
    for (int j = 1; j < NCP; j++) {
        float v = cl[b * NCP + j] - lz[j];
        if (v > bv) { bv = v; best = j; }
    }
    g_IDX[b] = best;
}
__global__ void dec1_kernel(const float* __restrict__ w1, const float* __restrict__ b1) {
    int b = blockIdx.x;    // 256
    int k = threadIdx.x;   // 512
    __shared__ float vs[16];
    __shared__ int idx;
    if (k == 0) idx = g_IDX[b];
    __syncthreads();
    if (k < 16) vs[k] = g_V[b * 160 + idx * 16 + k];
    __syncthreads();
    float acc = b1[k];
    const float* wp = &w1[(size_t)k * 160 + idx * 16];
#pragma unroll
    for (int o = 0; o < 16; o++) acc = fmaf(vs[o], wp[o], acc);
    g_H1h[b * DEC1 + k] = __float2bfloat16(fmaxf(acc, 0.f));
}

// ---------------- launch ----------------
extern "C" void kernel_launch(void* const* d_in, const int* in_sizes, int n_in,
                              void* d_out, int out_size) {
    const float* data    = (const float*)d_in[0];
    const float* conv1_w = (const float*)d_in[1];
    const float* conv1_b = (const float*)d_in[2];
    const float* prim_w  = (const float*)d_in[3];
    const float* prim_b  = (const float*)d_in[4];
    const float* W_digit = (const float*)d_in[5];
    const float* dec_w1  = (const float*)d_in[6];
    const float* dec_b1  = (const float*)d_in[7];
    const float* dec_w2  = (const float*)d_in[8];
    const float* dec_b2  = (const float*)d_in[9];
    const float* dec_w3  = (const float*)d_in[10];
    const float* dec_b3  = (const float*)d_in[11];
    float* out = (float*)d_out;

    __nv_bfloat16 *pA1h, *pW1h, *pC1h, *pW2h, *pH1h, *pH2h;
    float *pUp;
    cudaGetSymbolAddress((void**)&pA1h, g_A1h);
    cudaGetSymbolAddress((void**)&pW1h, g_W1h);
    cudaGetSymbolAddress((void**)&pC1h, g_C1h);
    cudaGetSymbolAddress((void**)&pW2h, g_W2h);
    cudaGetSymbolAddress((void**)&pH1h, g_H1h);
    cudaGetSymbolAddress((void**)&pH2h, g_H2h);
    cudaGetSymbolAddress((void**)&pUp, g_Up);

    constexpr int SMA3 = 3 * 20480;                 // conv1: 3-stage
    constexpr int SMA4 = 4 * 20480;                 // prim: 4-stage
    constexpr int SMB  = 2 * 20480;                 // wf 2-stage
    constexpr int SMR  = 512 * 81 * 4 + 5120 * 4;   // fused routing
    cudaFuncSetAttribute((const void*)hmma_gemm_async<0, 1, 2, 0, 3>, cudaFuncAttributeMaxDynamicSharedMemorySize, SMA3);
    cudaFuncSetAttribute((const void*)hmma_gemm_async<1, 0, 0, 1, 4>, cudaFuncAttributeMaxDynamicSharedMemorySize, SMA4);
    cudaFuncSetAttribute((const void*)hmma_gemm_wf<1, 2>, cudaFuncAttributeMaxDynamicSharedMemorySize, SMB);
    cudaFuncSetAttribute((const void*)hmma_gemm_wf<2, 0>, cudaFuncAttributeMaxDynamicSharedMemorySize, SMB);
    cudaFuncSetAttribute((const void*)route_fused_kernel<1, 1, 0>, cudaFuncAttributeMaxDynamicSharedMemorySize, SMR);
    cudaFuncSetAttribute((const void*)route_fused_kernel<0, 1, 0>, cudaFuncAttributeMaxDynamicSharedMemorySize, SMR);
    cudaFuncSetAttribute((const void*)route_fused_kernel<0, 0, 1>, cudaFuncAttributeMaxDynamicSharedMemorySize, SMR);

    // weight preps
    permute_w1_kernel<<<(256 * K1P + 255) / 256, 256>>>(conv1_w);
    permute_w2_kernel<<<256, 256>>>(prim_w);

    // 1) conv1: async bf16 HMMA (K=96, 3 stages), relu, bf16 out
    im2col1_kernel<<<(M1 * K1P + 255) / 256, 256>>>(data);
    hmma_gemm_async<0, 1, 2, 0, 3><<<dim3(M1 / 128, 256 / 128), 256, SMA3>>>(
        pA1h, pW1h, conv1_b, nullptr, pC1h, 256, K1P);

    // 2) primary caps: implicit im2col async (4 stages), split-K=4 partials
    hmma_gemm_async<1, 0, 0, 1, 4><<<dim3(M2 / 128, 256 / 128, ZSPL), 256, SMA4>>>(
        pC1h, pW2h, prim_b, pUp, nullptr, 256, K2);

    // 3) fused squash + u_hat (bf16 out)
    uhat_kernel<<<dim3(RTS, 8), 160>>>(W_digit);

    // 4) fused dynamic routing (softmax folded into route_fused; R11 structure)
    route_fused_kernel<1, 1, 0><<<BSZ, 512, SMR>>>(pUp);
    route_reduce_kernel<<<10, 512>>>(pUp, 1);
    route_fused_kernel<0, 1, 0><<<BSZ, 512, SMR>>>(pUp);
    route_reduce_kernel<<<10, 512>>>(pUp, 0);
    route_fused_kernel<0, 0, 1><<<BSZ, 512, SMR>>>(pUp);

    // 5) classes / mask / decoder
    classes_argmax_kernel<<<1, 256>>>();
    dec1_kernel<<<BSZ, DEC1>>>(dec_w1, dec_b1);
    hmma_gemm_wf<1, 2><<<dim3(BSZ / 128, DEC2 / 128), 256, SMB>>>(
        pH1h, dec_w2, dec_b2, nullptr, pH2h, DEC2, DEC1);
    hmma_gemm_wf<2, 0><<<dim3(BSZ / 128, RECS / 128), 256, SMB>>>(
        pH2h, dec_w3, dec_b3, out, nullptr, RECS, DEC2);
}

// round 15
// speedup vs baseline: 1.1248x; 1.0129x over previous
#include <cuda_runtime.h>
#include <cuda_bf16.h>
#include <math.h>
#include <stdint.h>

// ---------------- problem constants ----------------
#define BSZ   256
#define H1S   12
#define P1    144
#define RTS   512
#define NCP   10
#define K1P   96
#define K2    20736
#define M1    (BSZ*P1)    // 36864
#define M2    4096
#define RECS  102400
#define DEC1  512
#define DEC2  1024
#define ZSPL  4
#define USLICE (M2 * 256)

// ---------------- scratch ----------------
__device__ __nv_bfloat16 g_A1h[M1 * K1P];
__device__ __nv_bfloat16 g_W1h[256 * K1P];
__device__ __nv_bfloat16 g_C1h[M1 * 256];
__device__ __nv_bfloat16 g_W2h[256 * K2];
__device__ float         g_Up[ZSPL * USLICE];   // split-K partials; reused as agreement partials
__device__ __nv_bfloat16 g_H1h[BSZ * DEC1];
__device__ __nv_bfloat16 g_H2h[BSZ * DEC2];
__device__ __nv_bfloat16 g_UH[(size_t)BSZ * RTS * 160];
__device__ float g_BIJ[RTS * NCP];
__device__ float g_V [BSZ * 160];
__device__ int   g_IDX[BSZ];

// ---------------- helpers ----------------
__device__ __forceinline__ uint32_t smem_u32(const void* p) {
    uint32_t a;
    asm("{ .reg .u64 t; cvta.to.shared.u64 t, %1; cvt.u32.u64 %0, t; }" : "=r"(a) : "l"(p));
    return a;
}
__device__ __forceinline__ void ldsm_x4(uint32_t addr, uint32_t* r) {
    asm volatile("ldmatrix.sync.aligned.m8n8.x4.shared.b16 {%0,%1,%2,%3}, [%4];"
        : "=r"(r[0]), "=r"(r[1]), "=r"(r[2]), "=r"(r[3]) : "r"(addr));
}
__device__ __forceinline__ void mma_bf16(float* c, const uint32_t* a, const uint32_t* b) {
    asm volatile(
        "mma.sync.aligned.m16n8k16.row.col.f32.bf16.bf16.f32 "
        "{%0,%1,%2,%3}, {%4,%5,%6,%7}, {%8,%9}, {%0,%1,%2,%3};"
        : "+f"(c[0]), "+f"(c[1]), "+f"(c[2]), "+f"(c[3])
        : "r"(a[0]), "r"(a[1]), "r"(a[2]), "r"(a[3]), "r"(b[0]), "r"(b[1]));
}
__device__ __forceinline__ uint4 pack8bf16(float4 f0, float4 f1) {
    __nv_bfloat162 p0 = __halves2bfloat162(__float2bfloat16(f0.x), __float2bfloat16(f0.y));
    __nv_bfloat162 p1 = __halves2bfloat162(__float2bfloat16(f0.z), __float2bfloat16(f0.w));
    __nv_bfloat162 p2 = __halves2bfloat162(__float2bfloat16(f1.x), __float2bfloat16(f1.y));
    __nv_bfloat162 p3 = __halves2bfloat162(__float2bfloat16(f1.z), __float2bfloat16(f1.w));
    uint4 r;
    r.x = *reinterpret_cast<uint32_t*>(&p0);
    r.y = *reinterpret_cast<uint32_t*>(&p1);
    r.z = *reinterpret_cast<uint32_t*>(&p2);
    r.w = *reinterpret_cast<uint32_t*>(&p3);
    return r;
}
__device__ __forceinline__ void cp16(uint32_t d, const void* s) {
    asm volatile("cp.async.cg.shared.global [%0], [%1], 16;" :: "r"(d), "l"(s));
}
__device__ __forceinline__ void cp_commit() { asm volatile("cp.async.commit_group;"); }
template<int NW> __device__ __forceinline__ void cp_wait() {
    asm volatile("cp.async.wait_group %0;" :: "n"(NW));
}

// ============ async HMMA bf16 NT GEMM, BM=128 BN=128 BK=32, 256 thr (8 warps 4x2) ============
template<int MODE, int ACT, int OUT, int SPLITK, int STAGES>
__global__ __launch_bounds__(256)
void hmma_gemm_async(const __nv_bfloat16* __restrict__ Ah,
                     const __nv_bfloat16* __restrict__ Wh,
                     const float* __restrict__ bias,
                     float* __restrict__ Cf,
                     __nv_bfloat16* __restrict__ Coh,
                     int N, int K)
{
    extern __shared__ char sm[];
    constexpr int AP   = 80;
    constexpr int ABYT = 128 * AP;
    constexpr int STG  = 2 * ABYT;   // 20480

    const int t = threadIdx.x;
    const int m0 = blockIdx.x * 128;
    const int n0 = blockIdx.y * 128;
    const uint32_t sbase = smem_u32(sm);

    int r4[2], s4[2], mbase[2];
#pragma unroll
    for (int i = 0; i < 2; i++) {
        int idx = t + i * 256;
        r4[i] = idx >> 2; s4[i] = idx & 3;
        if (MODE == 1) {
            int m = m0 + r4[i]; int b = m >> 4, p = m & 15;
            mbase[i] = b * 144 + (p >> 2) * 12 + (p & 3);
        }
    }

    const int w = t >> 5, lane = t & 31;
    const int wm = w >> 1, wn = w & 1;          // 4x2 warps, 32x64 tile
    const int lrow = (lane & 7) + ((lane >> 3) & 1) * 8;
    const int lk   = ((lane >> 4) & 1) * 8;

    float acc[2][8][4];
#pragma unroll
    for (int mt = 0; mt < 2; mt++)
#pragma unroll
        for (int nt = 0; nt < 8; nt++)
#pragma unroll
            for (int q = 0; q < 4; q++) acc[mt][nt][q] = 0.f;

    auto issue = [&](int s, int k0) {
        uint32_t sb = sbase + (s % STAGES) * STG;
#pragma unroll
        for (int i = 0; i < 2; i++) {
            size_t aoff;
            if (MODE == 0) {
                aoff = (size_t)(m0 + r4[i]) * K + k0 + s4[i] * 8;
            } else {
                int rr = k0 >> 8;
                int rowg = mbase[i] + (rr / 9) * 12 + (rr % 9);
                aoff = (size_t)rowg * 256 + (k0 & 255) + s4[i] * 8;
            }
            cp16(sb + r4[i] * AP + s4[i] * 16, Ah + aoff);
            cp16(sb + ABYT + r4[i] * AP + s4[i] * 16,
                 Wh + (size_t)(n0 + r4[i]) * K + k0 + s4[i] * 8);
        }
    };
    auto compute = [&](int buf) {
        uint32_t base = sbase + buf * STG;
#pragma unroll
        for (int kk = 0; kk < 32; kk += 16) {
            uint32_t a_h[2][4], b_h[4][4];
#pragma unroll
            for (int mt = 0; mt < 2; mt++) {
                uint32_t ad = base + (wm * 32 + mt * 16 + lrow) * AP + (kk + lk) * 2;
                ldsm_x4(ad, a_h[mt]);
            }
#pragma unroll
            for (int np = 0; np < 4; np++) {
                uint32_t bd = base + ABYT + (wn * 64 + np * 16 + lrow) * AP + (kk + lk) * 2;
                ldsm_x4(bd, b_h[np]);
            }
#pragma unroll
            for (int mt = 0; mt < 2; mt++)
#pragma unroll
                for (int nt = 0; nt < 8; nt++)
                    mma_bf16(acc[mt][nt], a_h[mt], &b_h[nt >> 1][(nt & 1) * 2]);
        }
    };

    const int S = SPLITK ? (K / 32 / ZSPL) : (K / 32);
    const int kbase = SPLITK ? blockIdx.z * (K / ZSPL) : 0;
#pragma unroll
    for (int p = 0; p < STAGES - 1; p++) {
        if (p < S) issue(p, kbase + p * 32);
        cp_commit();
    }
    for (int s = 0; s < S; s++) {
        cp_wait<STAGES - 2>();
        __syncthreads();
        if (s + STAGES - 1 < S) issue(s + STAGES - 1, kbase + (s + STAGES - 1) * 32);
        cp_commit();
        compute(s % STAGES);
    }

    // ---- epilogue ----
    const size_t zoff = SPLITK ? (size_t)blockIdx.z * (size_t)(gridDim.x * 128) * N : 0;
#pragma unroll
    for (int mt = 0; mt < 2; mt++) {
#pragma unroll
        for (int nt = 0; nt < 8; nt++) {
            int row0 = m0 + wm * 32 + mt * 16 + (lane >> 2);
            int col  = n0 + wn * 64 + nt * 8 + (lane & 3) * 2;
            float b0, b1;
            if (SPLITK && blockIdx.z != 0) { b0 = 0.f; b1 = 0.f; }
            else { b0 = bias[col]; b1 = bias[col + 1]; }
#pragma unroll
            for (int half = 0; half < 2; half++) {
                int row = row0 + half * 8;
                float v0 = acc[mt][nt][half * 2 + 0] + b0;
                float v1 = acc[mt][nt][half * 2 + 1] + b1;
                if (ACT == 1) { v0 = fmaxf(v0, 0.f); v1 = fmaxf(v1, 0.f); }
                if (OUT == 0) {
                    *reinterpret_cast<float2*>(&Cf[zoff + (size_t)row * N + col]) = make_float2(v0, v1);
                } else {
                    *reinterpret_cast<__nv_bfloat162*>(&Coh[(size_t)row * N + col]) =
                        __halves2bfloat162(__float2bfloat16(v0), __float2bfloat16(v1));
                }
            }
        }
    }
}

// ============ 2-stage HMMA GEMM, fp32 W converted in loader, 256 thr ============
template<int ACT, int OUT>
__global__ __launch_bounds__(256)
void hmma_gemm_wf(const __nv_bfloat16* __restrict__ Ah,
                  const float* __restrict__ Wf,
                  const float* __restrict__ bias,
                  float* __restrict__ Cf,
                  __nv_bfloat16* __restrict__ Coh,
                  int N, int K)
{
    extern __shared__ char sm[];
    constexpr int AP   = 80;
    constexpr int ABYT = 128 * AP;
    constexpr int STG  = 2 * ABYT;

    const int t = threadIdx.x;
    const int m0 = blockIdx.x * 128;
    const int n0 = blockIdx.y * 128;
    const uint32_t sbase = smem_u32(sm);

    int r4[2], s4[2];
#pragma unroll
    for (int i = 0; i < 2; i++) {
        int idx = t + i * 256;
        r4[i] = idx >> 2; s4[i] = idx & 3;
    }
    const int w = t >> 5, lane = t & 31;
    const int wm = w >> 1, wn = w & 1;
    const int lrow = (lane & 7) + ((lane >> 3) & 1) * 8;
    const int lk   = ((lane >> 4) & 1) * 8;

    float acc[2][8][4];
#pragma unroll
    for (int mt = 0; mt < 2; mt++)
#pragma unroll
        for (int nt = 0; nt < 8; nt++)
#pragma unroll
            for (int q = 0; q < 4; q++) acc[mt][nt][q] = 0.f;

    uint4 rA[2], rB[2];
    auto ldg_stage = [&](int k0) {
#pragma unroll
        for (int i = 0; i < 2; i++) {
            rA[i] = *(const uint4*)(Ah + (size_t)(m0 + r4[i]) * K + k0 + s4[i] * 8);
            const float* wp = Wf + (size_t)(n0 + r4[i]) * K + k0 + s4[i] * 8;
            rB[i] = pack8bf16(*(const float4*)wp, *(const float4*)(wp + 4));
        }
    };
    auto sts_stage = [&](int buf) {
        char* p = sm + buf * STG;
#pragma unroll
        for (int i = 0; i < 2; i++) {
            *(uint4*)(p + r4[i] * AP + s4[i] * 16) = rA[i];
            *(uint4*)(p + ABYT + r4[i] * AP + s4[i] * 16) = rB[i];
        }
    };
    auto compute = [&](int buf) {
        uint32_t base = sbase + buf * STG;
#pragma unroll
        for (int kk = 0; kk < 32; kk += 16) {
            uint32_t a_h[2][4], b_h[4][4];
#pragma unroll
            for (int mt = 0; mt < 2; mt++) {
                uint32_t ad = base + (wm * 32 + mt * 16 + lrow) * AP + (kk + lk) * 2;
                ldsm_x4(ad, a_h[mt]);
            }
#pragma unroll
            for (int np = 0; np < 4; np++) {
                uint32_t bd = base + ABYT + (wn * 64 + np * 16 + lrow) * AP + (kk + lk) * 2;
                ldsm_x4(bd, b_h[np]);
            }
#pragma unroll
            for (int mt = 0; mt < 2; mt++)
#pragma unroll
                for (int nt = 0; nt < 8; nt++)
                    mma_bf16(acc[mt][nt], a_h[mt], &b_h[nt >> 1][(nt & 1) * 2]);
        }
    };

    const int S = K / 32;
    ldg_stage(0);
    sts_stage(0);
    __syncthreads();
    for (int s = 0; s < S; s++) {
        if (s + 1 < S) ldg_stage((s + 1) * 32);
        compute(s & 1);
        if (s + 1 < S) sts_stage((s + 1) & 1);
        __syncthreads();
    }

#pragma unroll
    for (int mt = 0; mt < 2; mt++) {
#pragma unroll
        for (int nt = 0; nt < 8; nt++) {
            int row0 = m0 + wm * 32 + mt * 16 + (lane >> 2);
            int col  = n0 + wn * 64 + nt * 8 + (lane & 3) * 2;
            float b0 = bias[col], b1 = bias[col + 1];
#pragma unroll
            for (int half = 0; half < 2; half++) {
                int row = row0 + half * 8;
                float v0 = acc[mt][nt][half * 2 + 0] + b0;
                float v1 = acc[mt][nt][half * 2 + 1] + b1;
                if (ACT == 1) { v0 = fmaxf(v0, 0.f); v1 = fmaxf(v1, 0.f); }
                else if (ACT == 2) {
                    v0 = 1.f / (1.f + expf(-v0));
                    v1 = 1.f / (1.f + expf(-v1));
                }
                if (OUT == 0) {
                    *reinterpret_cast<float2*>(&Cf[(size_t)row * N + col]) = make_float2(v0, v1);
                } else {
                    *reinterpret_cast<__nv_bfloat162*>(&Coh[(size_t)row * N + col]) =
                        __halves2bfloat162(__float2bfloat16(v0), __float2bfloat16(v1));
                }
            }
        }
    }
}

// ---------------- prep kernels ----------------
__global__ void im2col1_kernel(const float* __restrict__ data) {
    int idx = blockIdx.x * blockDim.x + threadIdx.x;
    if (idx >= M1 * K1P) return;
    int m = idx / K1P, kk = idx % K1P;
    float v = 0.f;
    if (kk < 81) {
        int b = m / P1, pos = m % P1;
        int y = pos / H1S, x = pos % H1S;
        int ky = kk / 9, kx = kk % 9;
        v = data[(size_t)b * 400 + (y + ky) * 20 + (x + kx)];
    }
    g_A1h[idx] = __float2bfloat16(v);
}
__global__ void permute_w1_kernel(const float* __restrict__ conv1_w) {
    int idx = blockIdx.x * blockDim.x + threadIdx.x;
    if (idx >= 256 * K1P) return;
    int o = idx / K1P, kk = idx % K1P;
    float v = (kk < 81) ? conv1_w[o * 81 + kk] : 0.f;
    g_W1h[idx] = __float2bfloat16(v);
}
__global__ void permute_w2_kernel(const float* __restrict__ prim_w) {
    __shared__ __nv_bfloat16 sm[K2];
    int o = blockIdx.x;
    int t = threadIdx.x;
    const float* src = prim_w + (size_t)o * K2;
    for (int idx = t; idx < K2; idx += 256)
        sm[idx] = __float2bfloat16(src[idx]);
    __syncthreads();
    __nv_bfloat16* dst = g_W2h + (size_t)o * K2;
    for (int idx = t; idx < K2; idx += 256) {
        int rr = idx >> 8, c = idx & 255;
        dst[idx] = sm[c * 81 + rr];
    }
}

// ---------------- fused squash + u_hat, 320 threads (2 batches in flight) ----------------
__global__ __launch_bounds__(320)
void uhat_kernel(const float* __restrict__ Wd) {
    int r = blockIdx.x;
    int b0 = blockIdx.y * 32;
    int t = threadIdx.x;          // 320
    int bb = t / 160, tt = t - bb * 160;   // bb in {0,1}, tt = c*16+o
    __shared__ float Wr[1280];
    __shared__ float Xr[256];
    for (int q = t; q < 1280; q += 320) Wr[q] = Wd[(size_t)r * 1280 + q];
    int oo = r >> 1, hi = r & 1;
    for (int q = t; q < 256; q += 320) {
        int b = q >> 3, i = q & 7;
        size_t base = (size_t)((b0 + b) * 16 + hi * 8 + i) * 256 + oo;
        float v = g_Up[base];
#pragma unroll
        for (int z = 1; z < ZSPL; z++) v += g_Up[(size_t)z * USLICE + base];
        Xr[q] = v;
    }
    __syncthreads();
    if (t < 32) {
        float u[8], sn = 0.f;
#pragma unroll
        for (int i = 0; i < 8; i++) { u[i] = Xr[t * 8 + i]; sn += u[i] * u[i]; }
        float sc = sn / ((1.f + sn) * sqrtf(sn));
#pragma unroll
        for (int i = 0; i < 8; i++) Xr[t * 8 + i] = u[i] * sc;
    }
    __syncthreads();
    for (int b = bb; b < 32; b += 2) {
        float acc = 0.f;
#pragma unroll
        for (int i = 0; i < 8; i++) acc = fmaf(Wr[tt * 8 + i], Xr[b * 8 + i], acc);
        g_UH[(size_t)((b0 + b) * RTS + r) * 160 + tt] = __float2bfloat16(acc);
    }
}

// ---- fused routing: one block per b; u_hat[b] smem-resident; softmax in-block ----
// s-phase split 3-way over routes (threads 0..479), then 3-term reduce.
template<int UNIFORM, int AGREE, int WRITEV>
__global__ __launch_bounds__(512)
void route_fused_kernel(float* __restrict__ agp) {
    extern __shared__ float smr[];               // [512*81] UH words, then cs[5120]
    float* cs = smr + 512 * 81;
    __shared__ float psum[3][160];
    __shared__ float v_s[160];
    __shared__ float s_mx[NCP], s_sum[NCP];
    const int b = blockIdx.x;
    const int t = threadIdx.x;
    const int w = t >> 5, lane = t & 31;

    const uint32_t* src = reinterpret_cast<const uint32_t*>(&g_UH[(size_t)b * RTS * 160]);
    uint32_t* uw = reinterpret_cast<uint32_t*>(smr);
    for (int q = t; q < RTS * 80; q += 512) {
        int r = q / 80, ww = q - r * 80;
        uw[r * 81 + ww] = src[q];
    }
    if (!UNIFORM) {
        for (int q = t; q < RTS * NCP; q += 512) cs[q] = g_BIJ[q];
    }
    __syncthreads();

    if (!UNIFORM) {
        if (w < NCP) {
            float m = -1e30f;
            for (int r = lane; r < RTS; r += 32) m = fmaxf(m, cs[r * NCP + w]);
#pragma unroll
            for (int o = 16; o; o >>= 1) m = fmaxf(m, __shfl_xor_sync(0xFFFFFFFFu, m, o));
            float ssum = 0.f;
            for (int r = lane; r < RTS; r += 32) ssum += expf(cs[r * NCP + w] - m);
#pragma unroll
            for (int o = 16; o; o >>= 1) ssum += __shfl_xor_sync(0xFFFFFFFFu, ssum, o);
            if (lane == 0) { s_mx[w] = m; s_sum[w] = ssum; }
        }
        __syncthreads();
        for (int q = t; q < RTS * NCP; q += 512) {
            int j = q % NCP;
            cs[q] = expf(cs[q] - s_mx[j]) / s_sum[j];
        }
        __syncthreads();
    }

    // s-phase: 3 route-groups in parallel
    {
        int g = t / 160;
        int tt = t - g * 160;
        if (g < 3) {
            int j = tt >> 4;
            int wdx = tt >> 1, hi = tt & 1;
            float acc = 0.f;
            for (int r = g; r < RTS; r += 3) {
                uint32_t u2 = uw[r * 81 + wdx];
                float2 a = __bfloat1622float2(*reinterpret_cast<__nv_bfloat162*>(&u2));
                float u = hi ? a.y : a.x;
                float c = UNIFORM ? (1.f / 512.f) : cs[r * NCP + j];
                acc = fmaf(c, u, acc);
            }
            psum[g][tt] = acc;
        }
    }
    __syncthreads();
    if (t < 160) {
        float acc = psum[0][t] + psum[1][t] + psum[2][t];
        float sq = acc * acc;
        float v = sq * acc / ((1.f + sq) * sqrtf(sq));
        v_s[t] = v;
        if (WRITEV) g_V[b * 160 + t] = v;
    }
    __syncthreads();

    if (AGREE) {
        int r = t;
        const uint32_t* row = uw + r * 81;
#pragma unroll
        for (int j = 0; j < NCP; j++) {
            float d = 0.f;
#pragma unroll
            for (int ww = 0; ww < 8; ww++) {
                uint32_t u2 = row[j * 8 + ww];
                float2 a = __bfloat1622float2(*reinterpret_cast<__nv_bfloat162*>(&u2));
                d += a.x * v_s[j * 16 + ww * 2] + a.y * v_s[j * 16 + ww * 2 + 1];
            }
            agp[(size_t)b * 5120 + j * 512 + r] = d;
        }
    }
}
__global__ void route_reduce_kernel(const float* __restrict__ agp, int first) {
    int q = blockIdx.x * 512 + threadIdx.x;   // 5120
    float s = 0.f;
    for (int b = 0; b < BSZ; b++) s += agp[(size_t)b * 5120 + q];
    int j = q >> 9, r = q & 511;
    float val = s * (1.f / 256.f);
    if (first) g_BIJ[r * NCP + j] = val;
    else       g_BIJ[r * NCP + j] += val;
}
__global__ void classes_argmax_kernel() {
    int b = threadIdx.x; // 256
    __shared__ float cl[256 * NCP];
    __shared__ float lz[NCP];
    for (int j = 0; j < NCP; j++) {
        float s = 0.f;
        for (int o = 0; o < 16; o++) {
            float v = g_V[b * 160 + j * 16 + o];
            s += v * v;
        }
        cl[b * NCP + j] = sqrtf(s);
    }
    __syncthreads();
    if (b < NCP) {
        float m = -1e30f;
        for (int q = 0; q < 256; q++) m = fmaxf(m, cl[q * NCP + b]);
        float s = 0.f;
        for (int q = 0; q < 256; q++) s += expf(cl[q * NCP + b] - m);
        lz[b] = m + logf(s);
    }
    __syncthreads();
    int best = 0;
    float bv = cl[b * NCP + 0] - lz[0];
    for (int j = 1; j < NCP; j++) {
        float v = cl[b * NCP + j] - lz[j];
        if (v > bv) { bv = v; best = j; }
    }
    g_IDX[b] = best;
}
__global__ void dec1_kernel(const float* __restrict__ w1, const float* __restrict__ b1) {
    int b = blockIdx.x;    // 256
    int k = threadIdx.x;   // 512
    __shared__ float vs[16];
    __shared__ int idx;
    if (k == 0) idx = g_IDX[b];
    __syncthreads();
    if (k < 16) vs[k] = g_V[b * 160 + idx * 16 + k];
    __syncthreads();
    float acc = b1[k];
    const float* wp = &w1[(size_t)k * 160 + idx * 16];
#pragma unroll
    for (int o = 0; o < 16; o++) acc = fmaf(vs[o], wp[o], acc);
    g_H1h[b * DEC1 + k] = __float2bfloat16(fmaxf(acc, 0.f));
}

// ---------------- launch ----------------
extern "C" void kernel_launch(void* const* d_in, const int* in_sizes, int n_in,
                              void* d_out, int out_size) {
    const float* data    = (const float*)d_in[0];
    const float* conv1_w = (const float*)d_in[1];
    const float* conv1_b = (const float*)d_in[2];
    const float* prim_w  = (const float*)d_in[3];
    const float* prim_b  = (const float*)d_in[4];
    const float* W_digit = (const float*)d_in[5];
    const float* dec_w1  = (const float*)d_in[6];
    const float* dec_b1  = (const float*)d_in[7];
    const float* dec_w2  = (const float*)d_in[8];
    const float* dec_b2  = (const float*)d_in[9];
    const float* dec_w3  = (const float*)d_in[10];
    const float* dec_b3  = (const float*)d_in[11];
    float* out = (float*)d_out;

    __nv_bfloat16 *pA1h, *pW1h, *pC1h, *pW2h, *pH1h, *pH2h;
    float *pUp;
    cudaGetSymbolAddress((void**)&pA1h, g_A1h);
    cudaGetSymbolAddress((void**)&pW1h, g_W1h);
    cudaGetSymbolAddress((void**)&pC1h, g_C1h);
    cudaGetSymbolAddress((void**)&pW2h, g_W2h);
    cudaGetSymbolAddress((void**)&pH1h, g_H1h);
    cudaGetSymbolAddress((void**)&pH2h, g_H2h);
    cudaGetSymbolAddress((void**)&pUp, g_Up);

    constexpr int SMA3 = 3 * 20480;                 // conv1: 3-stage
    constexpr int SMA4 = 4 * 20480;                 // prim: 4-stage
    constexpr int SMB  = 2 * 20480;                 // wf 2-stage
    constexpr int SMR  = 512 * 81 * 4 + 5120 * 4;   // fused routing
    cudaFuncSetAttribute((const void*)hmma_gemm_async<0, 1, 2, 0, 3>, cudaFuncAttributeMaxDynamicSharedMemorySize, SMA3);
    cudaFuncSetAttribute((const void*)hmma_gemm_async<1, 0, 0, 1, 4>, cudaFuncAttributeMaxDynamicSharedMemorySize, SMA4);
    cudaFuncSetAttribute((const void*)hmma_gemm_wf<1, 2>, cudaFuncAttributeMaxDynamicSharedMemorySize, SMB);
    cudaFuncSetAttribute((const void*)hmma_gemm_wf<2, 0>, cudaFuncAttributeMaxDynamicSharedMemorySize, SMB);
    cudaFuncSetAttribute((const void*)route_fused_kernel<1, 1, 0>, cudaFuncAttributeMaxDynamicSharedMemorySize, SMR);
    cudaFuncSetAttribute((const void*)route_fused_kernel<0, 1, 0>, cudaFuncAttributeMaxDynamicSharedMemorySize, SMR);
    cudaFuncSetAttribute((const void*)route_fused_kernel<0, 0, 1>, cudaFuncAttributeMaxDynamicSharedMemorySize, SMR);

    // weight preps
    permute_w1_kernel<<<(256 * K1P + 255) / 256, 256>>>(conv1_w);
    permute_w2_kernel<<<256, 256>>>(prim_w);

    // 1) conv1: async bf16 HMMA (K=96, 3 stages), relu, bf16 out
    im2col1_kernel<<<(M1 * K1P + 255) / 256, 256>>>(data);
    hmma_gemm_async<0, 1, 2, 0, 3><<<dim3(M1 / 128, 256 / 128), 256, SMA3>>>(
        pA1h, pW1h, conv1_b, nullptr, pC1h, 256, K1P);

    // 2) primary caps: implicit im2col async (4 stages), split-K=4 partials
    hmma_gemm_async<1, 0, 0, 1, 4><<<dim3(M2 / 128, 256 / 128, ZSPL), 256, SMA4>>>(
        pC1h, pW2h, prim_b, pUp, nullptr, 256, K2);

    // 3) fused squash + u_hat (bf16 out, 320 threads)
    uhat_kernel<<<dim3(RTS, 8), 320>>>(W_digit);

    // 4) fused dynamic routing
    route_fused_kernel<1, 1, 0><<<BSZ, 512, SMR>>>(pUp);
    route_reduce_kernel<<<10, 512>>>(pUp, 1);
    route_fused_kernel<0, 1, 0><<<BSZ, 512, SMR>>>(pUp);
    route_reduce_kernel<<<10, 512>>>(pUp, 0);
    route_fused_kernel<0, 0, 1><<<BSZ, 512, SMR>>>(pUp);

    // 5) classes / mask / decoder
    classes_argmax_kernel<<<1, 256>>>();
    dec1_kernel<<<BSZ, DEC1>>>(dec_w1, dec_b1);
    hmma_gemm_wf<1, 2><<<dim3(BSZ / 128, DEC2 / 128), 256, SMB>>>(
        pH1h, dec_w2, dec_b2, nullptr, pH2h, DEC2, DEC1);
    hmma_gemm_wf<2, 0><<<dim3(BSZ / 128, RECS / 128), 256, SMB>>>(
        pH2h, dec_w3, dec_b3, out, nullptr, RECS, DEC2);
}

// round 16
// speedup vs baseline: 1.2198x; 1.0845x over previous
#include <cuda_runtime.h>
#include <cuda_bf16.h>
#include <math.h>
#include <stdint.h>

// ---------------- problem constants ----------------
#define BSZ   256
#define H1S   12
#define P1    144
#define RTS   512
#define NCP   10
#define K1P   96
#define K2    20736
#define M1    (BSZ*P1)    // 36864
#define M2    4096
#define RECS  102400
#define DEC1  512
#define DEC2  1024
#define ZSPL  4
#define USLICE (M2 * 256)

// ---------------- scratch ----------------
__device__ __nv_bfloat16 g_A1h[M1 * K1P];
__device__ __nv_bfloat16 g_W1h[256 * K1P];
__device__ __nv_bfloat16 g_C1h[M1 * 256];
__device__ __nv_bfloat16 g_W2h[256 * K2];
__device__ float         g_Up[ZSPL * USLICE];   // split-K partials; reused as agreement partials
__device__ __nv_bfloat16 g_H1h[BSZ * DEC1];
__device__ __nv_bfloat16 g_H2h[BSZ * DEC2];
__device__ __nv_bfloat16 g_UH[(size_t)BSZ * RTS * 160];
__device__ float g_BIJ[RTS * NCP];
__device__ float g_V [BSZ * 160];
__device__ int   g_IDX[BSZ];

// ---------------- helpers ----------------
__device__ __forceinline__ uint32_t smem_u32(const void* p) {
    uint32_t a;
    asm("{ .reg .u64 t; cvta.to.shared.u64 t, %1; cvt.u32.u64 %0, t; }" : "=r"(a) : "l"(p));
    return a;
}
__device__ __forceinline__ void ldsm_x4(uint32_t addr, uint32_t* r) {
    asm volatile("ldmatrix.sync.aligned.m8n8.x4.shared.b16 {%0,%1,%2,%3}, [%4];"
        : "=r"(r[0]), "=r"(r[1]), "=r"(r[2]), "=r"(r[3]) : "r"(addr));
}
__device__ __forceinline__ void mma_bf16(float* c, const uint32_t* a, const uint32_t* b) {
    asm volatile(
        "mma.sync.aligned.m16n8k16.row.col.f32.bf16.bf16.f32 "
        "{%0,%1,%2,%3}, {%4,%5,%6,%7}, {%8,%9}, {%0,%1,%2,%3};"
        : "+f"(c[0]), "+f"(c[1]), "+f"(c[2]), "+f"(c[3])
        : "r"(a[0]), "r"(a[1]), "r"(a[2]), "r"(a[3]), "r"(b[0]), "r"(b[1]));
}
__device__ __forceinline__ uint4 pack8bf16(float4 f0, float4 f1) {
    __nv_bfloat162 p0 = __halves2bfloat162(__float2bfloat16(f0.x), __float2bfloat16(f0.y));
    __nv_bfloat162 p1 = __halves2bfloat162(__float2bfloat16(f0.z), __float2bfloat16(f0.w));
    __nv_bfloat162 p2 = __halves2bfloat162(__float2bfloat16(f1.x), __float2bfloat16(f1.y));
    __nv_bfloat162 p3 = __halves2bfloat162(__float2bfloat16(f1.z), __float2bfloat16(f1.w));
    uint4 r;
    r.x = *reinterpret_cast<uint32_t*>(&p0);
    r.y = *reinterpret_cast<uint32_t*>(&p1);
    r.z = *reinterpret_cast<uint32_t*>(&p2);
    r.w = *reinterpret_cast<uint32_t*>(&p3);
    return r;
}
__device__ __forceinline__ void cp16(uint32_t d, const void* s) {
    asm volatile("cp.async.cg.shared.global [%0], [%1], 16;" :: "r"(d), "l"(s));
}
__device__ __forceinline__ void cp_commit() { asm volatile("cp.async.commit_group;"); }
template<int NW> __device__ __forceinline__ void cp_wait() {
    asm volatile("cp.async.wait_group %0;" :: "n"(NW));
}

// ============ async HMMA bf16 NT GEMM, BM=128 BN=128 BK=32, 256 thr (8 warps 4x2) ============
template<int MODE, int ACT, int OUT, int SPLITK, int STAGES>
__global__ __launch_bounds__(256)
void hmma_gemm_async(const __nv_bfloat16* __restrict__ Ah,
                     const __nv_bfloat16* __restrict__ Wh,
                     const float* __restrict__ bias,
                     float* __restrict__ Cf,
                     __nv_bfloat16* __restrict__ Coh,
                     int N, int K)
{
    extern __shared__ char sm[];
    constexpr int AP   = 80;
    constexpr int ABYT = 128 * AP;
    constexpr int STG  = 2 * ABYT;   // 20480

    const int t = threadIdx.x;
    const int m0 = blockIdx.x * 128;
    const int n0 = blockIdx.y * 128;
    const uint32_t sbase = smem_u32(sm);

    int r4[2], s4[2], mbase[2];
#pragma unroll
    for (int i = 0; i < 2; i++) {
        int idx = t + i * 256;
        r4[i] = idx >> 2; s4[i] = idx & 3;
        if (MODE == 1) {
            int m = m0 + r4[i]; int b = m >> 4, p = m & 15;
            mbase[i] = b * 144 + (p >> 2) * 12 + (p & 3);
        }
    }

    const int w = t >> 5, lane = t & 31;
    const int wm = w >> 1, wn = w & 1;          // 4x2 warps, 32x64 tile
    const int lrow = (lane & 7) + ((lane >> 3) & 1) * 8;
    const int lk   = ((lane >> 4) & 1) * 8;

    float acc[2][8][4];
#pragma unroll
    for (int mt = 0; mt < 2; mt++)
#pragma unroll
        for (int nt = 0; nt < 8; nt++)
#pragma unroll
            for (int q = 0; q < 4; q++) acc[mt][nt][q] = 0.f;

    auto issue = [&](int s, int k0) {
        uint32_t sb = sbase + (s % STAGES) * STG;
#pragma unroll
        for (int i = 0; i < 2; i++) {
            size_t aoff;
            if (MODE == 0) {
                aoff = (size_t)(m0 + r4[i]) * K + k0 + s4[i] * 8;
            } else {
                int rr = k0 >> 8;
                int rowg = mbase[i] + (rr / 9) * 12 + (rr % 9);
                aoff = (size_t)rowg * 256 + (k0 & 255) + s4[i] * 8;
            }
            cp16(sb + r4[i] * AP + s4[i] * 16, Ah + aoff);
            cp16(sb + ABYT + r4[i] * AP + s4[i] * 16,
                 Wh + (size_t)(n0 + r4[i]) * K + k0 + s4[i] * 8);
        }
    };
    auto compute = [&](int buf) {
        uint32_t base = sbase + buf * STG;
#pragma unroll
        for (int kk = 0; kk < 32; kk += 16) {
            uint32_t a_h[2][4], b_h[4][4];
#pragma unroll
            for (int mt = 0; mt < 2; mt++) {
                uint32_t ad = base + (wm * 32 + mt * 16 + lrow) * AP + (kk + lk) * 2;
                ldsm_x4(ad, a_h[mt]);
            }
#pragma unroll
            for (int np = 0; np < 4; np++) {
                uint32_t bd = base + ABYT + (wn * 64 + np * 16 + lrow) * AP + (kk + lk) * 2;
                ldsm_x4(bd, b_h[np]);
            }
#pragma unroll
            for (int mt = 0; mt < 2; mt++)
#pragma unroll
                for (int nt = 0; nt < 8; nt++)
                    mma_bf16(acc[mt][nt], a_h[mt], &b_h[nt >> 1][(nt & 1) * 2]);
        }
    };

    const int S = SPLITK ? (K / 32 / ZSPL) : (K / 32);
    const int kbase = SPLITK ? blockIdx.z * (K / ZSPL) : 0;
#pragma unroll
    for (int p = 0; p < STAGES - 1; p++) {
        if (p < S) issue(p, kbase + p * 32);
        cp_commit();
    }
    for (int s = 0; s < S; s++) {
        cp_wait<STAGES - 2>();
        __syncthreads();
        if (s + STAGES - 1 < S) issue(s + STAGES - 1, kbase + (s + STAGES - 1) * 32);
        cp_commit();
        compute(s % STAGES);
    }

    // ---- epilogue ----
    const size_t zoff = SPLITK ? (size_t)blockIdx.z * (size_t)(gridDim.x * 128) * N : 0;
#pragma unroll
    for (int mt = 0; mt < 2; mt++) {
#pragma unroll
        for (int nt = 0; nt < 8; nt++) {
            int row0 = m0 + wm * 32 + mt * 16 + (lane >> 2);
            int col  = n0 + wn * 64 + nt * 8 + (lane & 3) * 2;
            float b0, b1;
            if (SPLITK && blockIdx.z != 0) { b0 = 0.f; b1 = 0.f; }
            else { b0 = bias[col]; b1 = bias[col + 1]; }
#pragma unroll
            for (int half = 0; half < 2; half++) {
                int row = row0 + half * 8;
                float v0 = acc[mt][nt][half * 2 + 0] + b0;
                float v1 = acc[mt][nt][half * 2 + 1] + b1;
                if (ACT == 1) { v0 = fmaxf(v0, 0.f); v1 = fmaxf(v1, 0.f); }
                if (OUT == 0) {
                    *reinterpret_cast<float2*>(&Cf[zoff + (size_t)row * N + col]) = make_float2(v0, v1);
                } else {
                    *reinterpret_cast<__nv_bfloat162*>(&Coh[(size_t)row * N + col]) =
                        __halves2bfloat162(__float2bfloat16(v0), __float2bfloat16(v1));
                }
            }
        }
    }
}

// ============ 2-stage HMMA GEMM, fp32 W converted in loader, 256 thr (dec2) ============
template<int ACT, int OUT>
__global__ __launch_bounds__(256)
void hmma_gemm_wf(const __nv_bfloat16* __restrict__ Ah,
                  const float* __restrict__ Wf,
                  const float* __restrict__ bias,
                  float* __restrict__ Cf,
                  __nv_bfloat16* __restrict__ Coh,
                  int N, int K)
{
    extern __shared__ char sm[];
    constexpr int AP   = 80;
    constexpr int ABYT = 128 * AP;
    constexpr int STG  = 2 * ABYT;

    const int t = threadIdx.x;
    const int m0 = blockIdx.x * 128;
    const int n0 = blockIdx.y * 128;
    const uint32_t sbase = smem_u32(sm);

    int r4[2], s4[2];
#pragma unroll
    for (int i = 0; i < 2; i++) {
        int idx = t + i * 256;
        r4[i] = idx >> 2; s4[i] = idx & 3;
    }
    const int w = t >> 5, lane = t & 31;
    const int wm = w >> 1, wn = w & 1;
    const int lrow = (lane & 7) + ((lane >> 3) & 1) * 8;
    const int lk   = ((lane >> 4) & 1) * 8;

    float acc[2][8][4];
#pragma unroll
    for (int mt = 0; mt < 2; mt++)
#pragma unroll
        for (int nt = 0; nt < 8; nt++)
#pragma unroll
            for (int q = 0; q < 4; q++) acc[mt][nt][q] = 0.f;

    uint4 rA[2], rB[2];
    auto ldg_stage = [&](int k0) {
#pragma unroll
        for (int i = 0; i < 2; i++) {
            rA[i] = *(const uint4*)(Ah + (size_t)(m0 + r4[i]) * K + k0 + s4[i] * 8);
            const float* wp = Wf + (size_t)(n0 + r4[i]) * K + k0 + s4[i] * 8;
            rB[i] = pack8bf16(*(const float4*)wp, *(const float4*)(wp + 4));
        }
    };
    auto sts_stage = [&](int buf) {
        char* p = sm + buf * STG;
#pragma unroll
        for (int i = 0; i < 2; i++) {
            *(uint4*)(p + r4[i] * AP + s4[i] * 16) = rA[i];
            *(uint4*)(p + ABYT + r4[i] * AP + s4[i] * 16) = rB[i];
        }
    };
    auto compute = [&](int buf) {
        uint32_t base = sbase + buf * STG;
#pragma unroll
        for (int kk = 0; kk < 32; kk += 16) {
            uint32_t a_h[2][4], b_h[4][4];
#pragma unroll
            for (int mt = 0; mt < 2; mt++) {
                uint32_t ad = base + (wm * 32 + mt * 16 + lrow) * AP + (kk + lk) * 2;
                ldsm_x4(ad, a_h[mt]);
            }
#pragma unroll
            for (int np = 0; np < 4; np++) {
                uint32_t bd = base + ABYT + (wn * 64 + np * 16 + lrow) * AP + (kk + lk) * 2;
                ldsm_x4(bd, b_h[np]);
            }
#pragma unroll
            for (int mt = 0; mt < 2; mt++)
#pragma unroll
                for (int nt = 0; nt < 8; nt++)
                    mma_bf16(acc[mt][nt], a_h[mt], &b_h[nt >> 1][(nt & 1) * 2]);
        }
    };

    const int S = K / 32;
    ldg_stage(0);
    sts_stage(0);
    __syncthreads();
    for (int s = 0; s < S; s++) {
        if (s + 1 < S) ldg_stage((s + 1) * 32);
        compute(s & 1);
        if (s + 1 < S) sts_stage((s + 1) & 1);
        __syncthreads();
    }

#pragma unroll
    for (int mt = 0; mt < 2; mt++) {
#pragma unroll
        for (int nt = 0; nt < 8; nt++) {
            int row0 = m0 + wm * 32 + mt * 16 + (lane >> 2);
            int col  = n0 + wn * 64 + nt * 8 + (lane & 3) * 2;
            float b0 = bias[col], b1 = bias[col + 1];
#pragma unroll
            for (int half = 0; half < 2; half++) {
                int row = row0 + half * 8;
                float v0 = acc[mt][nt][half * 2 + 0] + b0;
                float v1 = acc[mt][nt][half * 2 + 1] + b1;
                if (ACT == 1) { v0 = fmaxf(v0, 0.f); v1 = fmaxf(v1, 0.f); }
                else if (ACT == 2) {
                    v0 = 1.f / (1.f + expf(-v0));
                    v1 = 1.f / (1.f + expf(-v1));
                }
                if (OUT == 0) {
                    *reinterpret_cast<float2*>(&Cf[(size_t)row * N + col]) = make_float2(v0, v1);
                } else {
                    *reinterpret_cast<__nv_bfloat162*>(&Coh[(size_t)row * N + col]) =
                        __halves2bfloat162(__float2bfloat16(v0), __float2bfloat16(v1));
                }
            }
        }
    }
}

// ============ dec3: 3-stage cp.async GEMM with fp32-W staged + in-smem convert ============
// smem: A[3][10240] | Wf32[3][16384] | Bbf16[2][10240]  (100,352 B)
template<int ACT>
__global__ __launch_bounds__(256)
void hmma_gemm_wfa(const __nv_bfloat16* __restrict__ Ah,
                   const float* __restrict__ Wf,
                   const float* __restrict__ bias,
                   float* __restrict__ Cf,
                   int N, int K)
{
    extern __shared__ char sm[];
    constexpr int AP    = 80;
    constexpr int ABYT  = 128 * AP;       // 10240
    constexpr int AOFF  = 0;
    constexpr int WOFF  = 3 * ABYT;       // 30720
    constexpr int WBYT  = 16384;
    constexpr int BOFF  = WOFF + 3 * WBYT;// 79872
    constexpr int BBYT  = 128 * AP;

    const int t = threadIdx.x;
    const int m0 = blockIdx.x * 128;
    const int n0 = blockIdx.y * 128;
    const uint32_t sbase = smem_u32(sm);

    int r4[2], s4[2];
#pragma unroll
    for (int i = 0; i < 2; i++) {
        int idx = t + i * 256;
        r4[i] = idx >> 2; s4[i] = idx & 3;
    }
    const int w = t >> 5, lane = t & 31;
    const int wm = w >> 1, wn = w & 1;
    const int lrow = (lane & 7) + ((lane >> 3) & 1) * 8;
    const int lk   = ((lane >> 4) & 1) * 8;

    float acc[2][8][4];
#pragma unroll
    for (int mt = 0; mt < 2; mt++)
#pragma unroll
        for (int nt = 0; nt < 8; nt++)
#pragma unroll
            for (int q = 0; q < 4; q++) acc[mt][nt][q] = 0.f;

    auto issue = [&](int s, int k0) {
        uint32_t ab = sbase + AOFF + (s % 3) * ABYT;
        uint32_t wb = sbase + WOFF + (s % 3) * WBYT;
        // A tile: 128 x 32 bf16, pitch 80
#pragma unroll
        for (int i = 0; i < 2; i++) {
            cp16(ab + r4[i] * AP + s4[i] * 16,
                 Ah + (size_t)(m0 + r4[i]) * K + k0 + s4[i] * 8);
        }
        // W tile fp32: 128 rows x 32 fp32 = 128B/row, flat
#pragma unroll
        for (int j = 0; j < 4; j++) {
            int q = t + j * 256;
            int row = q >> 3, seg = q & 7;
            cp16(wb + row * 128 + seg * 16,
                 Wf + (size_t)(n0 + row) * K + k0 + seg * 4);
        }
    };
    auto convert = [&](int s) {
        const float2* wsrc = reinterpret_cast<const float2*>(sm + WOFF + (s % 3) * WBYT);
        char* bb = sm + BOFF + (s & 1) * BBYT;
#pragma unroll
        for (int i = 0; i < 8; i++) {
            int p = t + i * 256;            // pair index 0..2047
            int row = p >> 4, pc = p & 15;
            float2 f = wsrc[p];
            __nv_bfloat162 h = __halves2bfloat162(__float2bfloat16(f.x), __float2bfloat16(f.y));
            *reinterpret_cast<uint32_t*>(bb + row * AP + pc * 4) =
                *reinterpret_cast<uint32_t*>(&h);
        }
    };
    auto compute = [&](int s) {
        uint32_t abase = sbase + AOFF + (s % 3) * ABYT;
        uint32_t bbase = sbase + BOFF + (s & 1) * BBYT;
#pragma unroll
        for (int kk = 0; kk < 32; kk += 16) {
            uint32_t a_h[2][4], b_h[4][4];
#pragma unroll
            for (int mt = 0; mt < 2; mt++) {
                uint32_t ad = abase + (wm * 32 + mt * 16 + lrow) * AP + (kk + lk) * 2;
                ldsm_x4(ad, a_h[mt]);
            }
#pragma unroll
            for (int np = 0; np < 4; np++) {
                uint32_t bd = bbase + (wn * 64 + np * 16 + lrow) * AP + (kk + lk) * 2;
                ldsm_x4(bd, b_h[np]);
            }
#pragma unroll
            for (int mt = 0; mt < 2; mt++)
#pragma unroll
                for (int nt = 0; nt < 8; nt++)
                    mma_bf16(acc[mt][nt], a_h[mt], &b_h[nt >> 1][(nt & 1) * 2]);
        }
    };

    const int S = K / 32;
    issue(0, 0); cp_commit();
    issue(1, 32); cp_commit();
    for (int s = 0; s < S; s++) {
        cp_wait<1>();
        __syncthreads();
        if (s + 2 < S) issue(s + 2, (s + 2) * 32);
        cp_commit();
        convert(s);
        __syncthreads();
        compute(s);
    }

#pragma unroll
    for (int mt = 0; mt < 2; mt++) {
#pragma unroll
        for (int nt = 0; nt < 8; nt++) {
            int row0 = m0 + wm * 32 + mt * 16 + (lane >> 2);
            int col  = n0 + wn * 64 + nt * 8 + (lane & 3) * 2;
            float b0 = bias[col], b1 = bias[col + 1];
#pragma unroll
            for (int half = 0; half < 2; half++) {
                int row = row0 + half * 8;
                float v0 = acc[mt][nt][half * 2 + 0] + b0;
                float v1 = acc[mt][nt][half * 2 + 1] + b1;
                if (ACT == 2) {
                    v0 = 1.f / (1.f + expf(-v0));
                    v1 = 1.f / (1.f + expf(-v1));
                } else if (ACT == 1) {
                    v0 = fmaxf(v0, 0.f); v1 = fmaxf(v1, 0.f);
                }
                *reinterpret_cast<float2*>(&Cf[(size_t)row * N + col]) = make_float2(v0, v1);
            }
        }
    }
}

// ---------------- prep kernels ----------------
__global__ void im2col1_kernel(const float* __restrict__ data) {
    int idx = blockIdx.x * blockDim.x + threadIdx.x;
    if (idx >= M1 * K1P) return;
    int m = idx / K1P, kk = idx % K1P;
    float v = 0.f;
    if (kk < 81) {
        int b = m / P1, pos = m % P1;
        int y = pos / H1S, x = pos % H1S;
        int ky = kk / 9, kx = kk % 9;
        v = data[(size_t)b * 400 + (y + ky) * 20 + (x + kx)];
    }
    g_A1h[idx] = __float2bfloat16(v);
}
__global__ void permute_w1_kernel(const float* __restrict__ conv1_w) {
    int idx = blockIdx.x * blockDim.x + threadIdx.x;
    if (idx >= 256 * K1P) return;
    int o = idx / K1P, kk = idx % K1P;
    float v = (kk < 81) ? conv1_w[o * 81 + kk] : 0.f;
    g_W1h[idx] = __float2bfloat16(v);
}
__global__ void permute_w2_kernel(const float* __restrict__ prim_w) {
    __shared__ __nv_bfloat16 sm[K2];
    int o = blockIdx.x;
    int t = threadIdx.x;
    const float* src = prim_w + (size_t)o * K2;
    for (int idx = t; idx < K2; idx += 256)
        sm[idx] = __float2bfloat16(src[idx]);
    __syncthreads();
    __nv_bfloat16* dst = g_W2h + (size_t)o * K2;
    for (int idx = t; idx < K2; idx += 256) {
        int rr = idx >> 8, c = idx & 255;
        dst[idx] = sm[c * 81 + rr];
    }
}

// ---------------- fused squash + u_hat, 320 threads ----------------
__global__ __launch_bounds__(320)
void uhat_kernel(const float* __restrict__ Wd) {
    int r = blockIdx.x;
    int b0 = blockIdx.y * 32;
    int t = threadIdx.x;
    int bb = t / 160, tt = t - bb * 160;
    __shared__ float Wr[1280];
    __shared__ float Xr[256];
    for (int q = t; q < 1280; q += 320) Wr[q] = Wd[(size_t)r * 1280 + q];
    int oo = r >> 1, hi = r & 1;
    for (int q = t; q < 256; q += 320) {
        int b = q >> 3, i = q & 7;
        size_t base = (size_t)((b0 + b) * 16 + hi * 8 + i) * 256 + oo;
        float v = g_Up[base];
#pragma unroll
        for (int z = 1; z < ZSPL; z++) v += g_Up[(size_t)z * USLICE + base];
        Xr[q] = v;
    }
    __syncthreads();
    if (t < 32) {
        float u[8], sn = 0.f;
#pragma unroll
        for (int i = 0; i < 8; i++) { u[i] = Xr[t * 8 + i]; sn += u[i] * u[i]; }
        float sc = sn / ((1.f + sn) * sqrtf(sn));
#pragma unroll
        for (int i = 0; i < 8; i++) Xr[t * 8 + i] = u[i] * sc;
    }
    __syncthreads();
    for (int b = bb; b < 32; b += 2) {
        float acc = 0.f;
#pragma unroll
        for (int i = 0; i < 8; i++) acc = fmaf(Wr[tt * 8 + i], Xr[b * 8 + i], acc);
        g_UH[(size_t)((b0 + b) * RTS + r) * 160 + tt] = __float2bfloat16(acc);
    }
}

// ---- fused routing: one block per b; u_hat[b] smem-resident; softmax in-block ----
template<int UNIFORM, int AGREE, int WRITEV>
__global__ __launch_bounds__(512)
void route_fused_kernel(float* __restrict__ agp) {
    extern __shared__ float smr[];
    float* cs = smr + 512 * 81;
    __shared__ float psum[3][160];
    __shared__ float v_s[160];
    __shared__ float s_mx[NCP], s_sum[NCP];
    const int b = blockIdx.x;
    const int t = threadIdx.x;
    const int w = t >> 5, lane = t & 31;

    const uint32_t* src = reinterpret_cast<const uint32_t*>(&g_UH[(size_t)b * RTS * 160]);
    uint32_t* uw = reinterpret_cast<uint32_t*>(smr);
    for (int q = t; q < RTS * 80; q += 512) {
        int r = q / 80, ww = q - r * 80;
        uw[r * 81 + ww] = src[q];
    }
    if (!UNIFORM) {
        for (int q = t; q < RTS * NCP; q += 512) cs[q] = g_BIJ[q];
    }
    __syncthreads();

    if (!UNIFORM) {
        if (w < NCP) {
            float m = -1e30f;
            for (int r = lane; r < RTS; r += 32) m = fmaxf(m, cs[r * NCP + w]);
#pragma unroll
            for (int o = 16; o; o >>= 1) m = fmaxf(m, __shfl_xor_sync(0xFFFFFFFFu, m, o));
            float ssum = 0.f;
            for (int r = lane; r < RTS; r += 32) ssum += expf(cs[r * NCP + w] - m);
#pragma unroll
            for (int o = 16; o; o >>= 1) ssum += __shfl_xor_sync(0xFFFFFFFFu, ssum, o);
            if (lane == 0) { s_mx[w] = m; s_sum[w] = ssum; }
        }
        __syncthreads();
        for (int q = t; q < RTS * NCP; q += 512) {
            int j = q % NCP;
            cs[q] = expf(cs[q] - s_mx[j]) / s_sum[j];
        }
        __syncthreads();
    }

    {
        int g = t / 160;
        int tt = t - g * 160;
        if (g < 3) {
            int j = tt >> 4;
            int wdx = tt >> 1, hi = tt & 1;
            float acc = 0.f;
            for (int r = g; r < RTS; r += 3) {
                uint32_t u2 = uw[r * 81 + wdx];
                float2 a = __bfloat1622float2(*reinterpret_cast<__nv_bfloat162*>(&u2));
                float u = hi ? a.y : a.x;
                float c = UNIFORM ? (1.f / 512.f) : cs[r * NCP + j];
                acc = fmaf(c, u, acc);
            }
            psum[g][tt] = acc;
        }
    }
    __syncthreads();
    if (t < 160) {
        float acc = psum[0][t] + psum[1][t] + psum[2][t];
        float sq = acc * acc;
        float v = sq * acc / ((1.f + sq) * sqrtf(sq));
        v_s[t] = v;
        if (WRITEV) g_V[b * 160 + t] = v;
    }
    __syncthreads();

    if (AGREE) {
        int r = t;
        const uint32_t* row = uw + r * 81;
#pragma unroll
        for (int j = 0; j < NCP; j++) {
            float d = 0.f;
#pragma unroll
            for (int ww = 0; ww < 8; ww++) {
                uint32_t u2 = row[j * 8 + ww];
                float2 a = __bfloat1622float2(*reinterpret_cast<__nv_bfloat162*>(&u2));
                d += a.x * v_s[j * 16 + ww * 2] + a.y * v_s[j * 16 + ww * 2 + 1];
            }
            agp[(size_t)b * 5120 + j * 512 + r] = d;
        }
    }
}
__global__ void route_reduce_kernel(const float* __restrict__ agp, int first) {
    int q = blockIdx.x * 512 + threadIdx.x;
    float s = 0.f;
    for (int b = 0; b < BSZ; b++) s += agp[(size_t)b * 5120 + q];
    int j = q >> 9, r = q & 511;
    float val = s * (1.f / 256.f);
    if (first) g_BIJ[r * NCP + j] = val;
    else       g_BIJ[r * NCP + j] += val;
}
__global__ void classes_argmax_kernel() {
    int b = threadIdx.x;
    __shared__ float cl[256 * NCP];
    __shared__ float lz[NCP];
    for (int j = 0; j < NCP; j++) {
        float s = 0.f;
        for (int o = 0; o < 16; o++) {
            float v = g_V[b * 160 + j * 16 + o];
            s += v * v;
        }
        cl[b * NCP + j] = sqrtf(s);
    }
    __syncthreads();
    if (b < NCP) {
        float m = -1e30f;
        for (int q = 0; q < 256; q++) m = fmaxf(m, cl[q * NCP + b]);
        float s = 0.f;
        for (int q = 0; q < 256; q++) s += expf(cl[q * NCP + b] - m);
        lz[b] = m + logf(s);
    }
    __syncthreads();
    int best = 0;
    float bv = cl[b * NCP + 0] - lz[0];
    for (int j = 1; j < NCP; j++) {
        float v = cl[b * NCP + j] - lz[j];
        if (v > bv) { bv = v; best = j; }
    }
    g_IDX[b] = best;
}
__global__ void dec1_kernel(const float* __restrict__ w1, const float* __restrict__ b1) {
    int b = blockIdx.x;
    int k = threadIdx.x;
    __shared__ float vs[16];
    __shared__ int idx;
    if (k == 0) idx = g_IDX[b];
    __syncthreads();
    if (k < 16) vs[k] = g_V[b * 160 + idx * 16 + k];
    __syncthreads();
    float acc = b1[k];
    const float* wp = &w1[(size_t)k * 160 + idx * 16];
#pragma unroll
    for (int o = 0; o < 16; o++) acc = fmaf(vs[o], wp[o], acc);
    g_H1h[b * DEC1 + k] = __float2bfloat16(fmaxf(acc, 0.f));
}

// ---------------- launch ----------------
extern "C" void kernel_launch(void* const* d_in, const int* in_sizes, int n_in,
                              void* d_out, int out_size) {
    const float* data    = (const float*)d_in[0];
    const float* conv1_w = (const float*)d_in[1];
    const float* conv1_b = (const float*)d_in[2];
    const float* prim_w  = (const float*)d_in[3];
    const float* prim_b  = (const float*)d_in[4];
    const float* W_digit = (const float*)d_in[5];
    const float* dec_w1  = (const float*)d_in[6];
    const float* dec_b1  = (const float*)d_in[7];
    const float* dec_w2  = (const float*)d_in[8];
    const float* dec_b2  = (const float*)d_in[9];
    const float* dec_w3  = (const float*)d_in[10];
    const float* dec_b3  = (const float*)d_in[11];
    float* out = (float*)d_out;

    __nv_bfloat16 *pA1h, *pW1h, *pC1h, *pW2h, *pH1h, *pH2h;
    float *pUp;
    cudaGetSymbolAddress((void**)&pA1h, g_A1h);
    cudaGetSymbolAddress((void**)&pW1h, g_W1h);
    cudaGetSymbolAddress((void**)&pC1h, g_C1h);
    cudaGetSymbolAddress((void**)&pW2h, g_W2h);
    cudaGetSymbolAddress((void**)&pH1h, g_H1h);
    cudaGetSymbolAddress((void**)&pH2h, g_H2h);
    cudaGetSymbolAddress((void**)&pUp, g_Up);

    constexpr int SMA3 = 3 * 20480;                 // conv1: 3-stage
    constexpr int SMA4 = 4 * 20480;                 // prim: 4-stage
    constexpr int SMB  = 2 * 20480;                 // dec2 wf 2-stage
    constexpr int SMW  = 3 * 10240 + 3 * 16384 + 2 * 10240;  // dec3 wfa: 100352
    constexpr int SMR  = 512 * 81 * 4 + 5120 * 4;   // fused routing
    cudaFuncSetAttribute((const void*)hmma_gemm_async<0, 1, 2, 0, 3>, cudaFuncAttributeMaxDynamicSharedMemorySize, SMA3);
    cudaFuncSetAttribute((const void*)hmma_gemm_async<1, 0, 0, 1, 4>, cudaFuncAttributeMaxDynamicSharedMemorySize, SMA4);
    cudaFuncSetAttribute((const void*)hmma_gemm_wf<1, 2>, cudaFuncAttributeMaxDynamicSharedMemorySize, SMB);
    cudaFuncSetAttribute((const void*)hmma_gemm_wfa<2>, cudaFuncAttributeMaxDynamicSharedMemorySize, SMW);
    cudaFuncSetAttribute((const void*)route_fused_kernel<1, 1, 0>, cudaFuncAttributeMaxDynamicSharedMemorySize, SMR);
    cudaFuncSetAttribute((const void*)route_fused_kernel<0, 1, 0>, cudaFuncAttributeMaxDynamicSharedMemorySize, SMR);
    cudaFuncSetAttribute((const void*)route_fused_kernel<0, 0, 1>, cudaFuncAttributeMaxDynamicSharedMemorySize, SMR);

    // weight preps
    permute_w1_kernel<<<(256 * K1P + 255) / 256, 256>>>(conv1_w);
    permute_w2_kernel<<<256, 256>>>(prim_w);

    // 1) conv1: async bf16 HMMA (K=96, 3 stages), relu, bf16 out
    im2col1_kernel<<<(M1 * K1P + 255) / 256, 256>>>(data);
    hmma_gemm_async<0, 1, 2, 0, 3><<<dim3(M1 / 128, 256 / 128), 256, SMA3>>>(
        pA1h, pW1h, conv1_b, nullptr, pC1h, 256, K1P);

    // 2) primary caps: implicit im2col async (4 stages), split-K=4 partials
    hmma_gemm_async<1, 0, 0, 1, 4><<<dim3(M2 / 128, 256 / 128, ZSPL), 256, SMA4>>>(
        pC1h, pW2h, prim_b, pUp, nullptr, 256, K2);

    // 3) fused squash + u_hat (bf16 out)
    uhat_kernel<<<dim3(RTS, 8), 320>>>(W_digit);

    // 4) fused dynamic routing
    route_fused_kernel<1, 1, 0><<<BSZ, 512, SMR>>>(pUp);
    route_reduce_kernel<<<10, 512>>>(pUp, 1);
    route_fused_kernel<0, 1, 0><<<BSZ, 512, SMR>>>(pUp);
    route_reduce_kernel<<<10, 512>>>(pUp, 0);
    route_fused_kernel<0, 0, 1><<<BSZ, 512, SMR>>>(pUp);

    // 5) classes / mask / decoder (dec3 on the async fp32-W pipeline)
    classes_argmax_kernel<<<1, 256>>>();
    dec1_kernel<<<BSZ, DEC1>>>(dec_w1, dec_b1);
    hmma_gemm_wf<1, 2><<<dim3(BSZ / 128, DEC2 / 128), 256, SMB>>>(
        pH1h, dec_w2, dec_b2, nullptr, pH2h, DEC2, DEC1);
    hmma_gemm_wfa<2><<<dim3(BSZ / 128, RECS / 128), 256, SMW>>>(
        pH2h, dec_w3, dec_b3, out, RECS, DEC2);
}